// round 3
// baseline (speedup 1.0000x reference)
#include <cuda_runtime.h>
#include <cuda_bf16.h>
#include <cstdint>

typedef unsigned short u16;
typedef unsigned int   u32;
typedef unsigned long long u64;

#define NTOK 8192
#define DIM  1024
#define HID  2048
#define NE   8
#define MAXROWS 17408
#define MAXMT 136

__device__ int   g_counts[NE], g_fill[NE], g_seg[NE + 1], g_ntiles;
__device__ int   g_tile_expert[MAXMT], g_tile_row0[MAXMT];
__device__ int   g_row_token[MAXROWS];
__device__ float g_row_coef[MAXROWS];
__device__ int   g_token_row[NTOK * 2];
__device__ int   g_tok_e[NTOK * 2];
__device__ float g_tok_p[NTOK * 2];

__device__ __align__(16) u16 g_Xhi[(size_t)MAXROWS * DIM];
__device__ __align__(16) u16 g_Xlo[(size_t)MAXROWS * DIM];
__device__ __align__(16) u16 g_W1hi[(size_t)NE * HID * DIM];
__device__ __align__(16) u16 g_W1lo[(size_t)NE * HID * DIM];
__device__ __align__(16) u16 g_W3hi[(size_t)NE * HID * DIM];
__device__ __align__(16) u16 g_W3lo[(size_t)NE * HID * DIM];
__device__ __align__(16) u16 g_W2hi[(size_t)NE * DIM * HID];
__device__ __align__(16) u16 g_W2lo[(size_t)NE * DIM * HID];
__device__ __align__(16) u16 g_Hhi[(size_t)MAXROWS * HID];
__device__ __align__(16) u16 g_Hlo[(size_t)MAXROWS * HID];
__device__ __align__(16) float g_Orows[(size_t)MAXROWS * DIM];

__device__ __forceinline__ u16 f2bf(float f) { return __bfloat16_as_ushort(__float2bfloat16(f)); }
__device__ __forceinline__ float bf2f(u16 u) { return __bfloat162float(__ushort_as_bfloat16(u)); }
__device__ __forceinline__ u32 pk(u16 a, u16 b) { return (u32)a | ((u32)b << 16); }

__device__ __forceinline__ u32 smem_u32(const void* p) {
    u32 a;
    asm("{ .reg .u64 t; cvta.to.shared.u64 t, %1; cvt.u32.u64 %0, t; }" : "=r"(a) : "l"(p));
    return a;
}
__device__ __forceinline__ void cpa16(u32 dst, const void* src) {
    asm volatile("cp.async.ca.shared.global [%0], [%1], 16;" :: "r"(dst), "l"(src) : "memory");
}
__device__ __forceinline__ void cpa_commit() { asm volatile("cp.async.commit_group;" ::: "memory"); }
__device__ __forceinline__ void cpa_wait2() { asm volatile("cp.async.wait_group 2;" ::: "memory"); }

__device__ __forceinline__ void ldsm4(u32* r, u32 addr) {
    asm volatile("ldmatrix.sync.aligned.m8n8.x4.shared.b16 {%0,%1,%2,%3}, [%4];"
                 : "=r"(r[0]), "=r"(r[1]), "=r"(r[2]), "=r"(r[3]) : "r"(addr));
}
__device__ __forceinline__ void ldsm2(u32* r, u32 addr) {
    asm volatile("ldmatrix.sync.aligned.m8n8.x2.shared.b16 {%0,%1}, [%2];"
                 : "=r"(r[0]), "=r"(r[1]) : "r"(addr));
}
__device__ __forceinline__ void mma16816(float* c, const u32* a, const u32* b) {
    asm volatile(
        "mma.sync.aligned.m16n8k16.row.col.f32.bf16.bf16.f32 "
        "{%0,%1,%2,%3}, {%4,%5,%6,%7}, {%8,%9}, {%0,%1,%2,%3};"
        : "+f"(c[0]), "+f"(c[1]), "+f"(c[2]), "+f"(c[3])
        : "r"(a[0]), "r"(a[1]), "r"(a[2]), "r"(a[3]), "r"(b[0]), "r"(b[1]));
}

// ---------------- routing / prep kernels ----------------
__global__ void k_init() {
    int i = blockIdx.x * 256 + threadIdx.x;
    if (i < MAXROWS) { g_row_token[i] = -1; g_row_coef[i] = 0.f; }
    if (i < NE) { g_counts[i] = 0; g_fill[i] = 0; }
}

__global__ void k_split(const float* __restrict__ src, int which) {
    u16 *hi, *lo;
    if (which == 0)      { hi = g_W1hi; lo = g_W1lo; }
    else if (which == 1) { hi = g_W3hi; lo = g_W3lo; }
    else                 { hi = g_W2hi; lo = g_W2lo; }
    size_t i = ((size_t)blockIdx.x * 256 + threadIdx.x) * 4;
    float4 v = *(const float4*)(src + i);
    u16 h0 = f2bf(v.x), h1 = f2bf(v.y), h2 = f2bf(v.z), h3 = f2bf(v.w);
    u16 l0 = f2bf(v.x - bf2f(h0)), l1 = f2bf(v.y - bf2f(h1));
    u16 l2 = f2bf(v.z - bf2f(h2)), l3 = f2bf(v.w - bf2f(h3));
    *(uint2*)(hi + i) = make_uint2(pk(h0, h1), pk(h2, h3));
    *(uint2*)(lo + i) = make_uint2(pk(l0, l1), pk(l2, l3));
}

__global__ void k_gate(const float* __restrict__ x, const float* __restrict__ gw,
                       const float* __restrict__ gb) {
    int w = (blockIdx.x * blockDim.x + threadIdx.x) >> 5;
    int lane = threadIdx.x & 31;
    if (w >= NTOK) return;
    const float* xr = x + (size_t)w * DIM;
    float acc[NE];
#pragma unroll
    for (int e = 0; e < NE; e++) acc[e] = 0.f;
    for (int j = lane; j < DIM; j += 32) {
        float xv = xr[j];
#pragma unroll
        for (int e = 0; e < NE; e++) acc[e] = fmaf(xv, gw[e * DIM + j], acc[e]);
    }
#pragma unroll
    for (int e = 0; e < NE; e++)
#pragma unroll
        for (int o = 16; o; o >>= 1) acc[e] += __shfl_xor_sync(0xffffffffu, acc[e], o);
    if (lane == 0) {
#pragma unroll
        for (int e = 0; e < NE; e++) acc[e] += gb[e];
        int e0 = 0;
#pragma unroll
        for (int e = 1; e < NE; e++) if (acc[e] > acc[e0]) e0 = e;
        int e1 = (e0 == 0) ? 1 : 0;
#pragma unroll
        for (int e = 0; e < NE; e++) if (e != e0 && acc[e] > acc[e1]) e1 = e;
        float p0 = 1.f / (1.f + expf(acc[e1] - acc[e0]));
        g_tok_e[2 * w] = e0; g_tok_e[2 * w + 1] = e1;
        g_tok_p[2 * w] = p0; g_tok_p[2 * w + 1] = 1.f - p0;
        atomicAdd(&g_counts[e0], 1);
        atomicAdd(&g_counts[e1], 1);
    }
}

__global__ void k_offsets() {
    int off = 0, nt = 0;
    for (int e = 0; e < NE; e++) {
        g_seg[e] = off;
        int t = (g_counts[e] + 127) >> 7;
        for (int m = 0; m < t; m++) { g_tile_expert[nt] = e; g_tile_row0[nt] = off + (m << 7); nt++; }
        off += t << 7;
    }
    g_seg[NE] = off;
    g_ntiles = nt;
}

__global__ void k_assign() {
    int t = blockIdx.x * 256 + threadIdx.x;
    if (t >= NTOK) return;
#pragma unroll
    for (int k = 0; k < 2; k++) {
        int e = g_tok_e[2 * t + k];
        int row = g_seg[e] + atomicAdd(&g_fill[e], 1);
        g_row_token[row] = t;
        g_row_coef[row] = g_tok_p[2 * t + k];
        g_token_row[2 * t + k] = row;
    }
}

__global__ void k_gather(const float* __restrict__ x) {
    int row = blockIdx.x;
    int t = g_row_token[row];
    size_t off = (size_t)row * DIM + threadIdx.x * 4;
    float4 v = make_float4(0.f, 0.f, 0.f, 0.f);
    if (t >= 0) v = *(const float4*)(x + (size_t)t * DIM + threadIdx.x * 4);
    u16 h0 = f2bf(v.x), h1 = f2bf(v.y), h2 = f2bf(v.z), h3 = f2bf(v.w);
    u16 l0 = f2bf(v.x - bf2f(h0)), l1 = f2bf(v.y - bf2f(h1));
    u16 l2 = f2bf(v.z - bf2f(h2)), l3 = f2bf(v.w - bf2f(h3));
    *(uint2*)(g_Xhi + off) = make_uint2(pk(h0, h1), pk(h2, h3));
    *(uint2*)(g_Xlo + off) = make_uint2(pk(l0, l1), pk(l2, l3));
}

// ---------------- GEMM13: H = relu(X W1^T)^2 * (X W3^T) ----------------
// CTA 128(M) x 64(N hidden), BK=32, 3-stage cp.async, rows padded to 80B.
#define RS 80
#define S13_AH 0
#define S13_AL 10240
#define S13_B1H 20480
#define S13_B1L 25600
#define S13_B3H 30720
#define S13_B3L 35840
#define SS13 40960
#define SMEM13 (3 * SS13)

__device__ __forceinline__ void load13(u32 sbase, int stage, int kt,
                                       const u16* Ah, const u16* Al,
                                       size_t wbase, int tid) {
    int k0 = kt * 32;
    u32 st = sbase + stage * SS13;
    for (int c = tid; c < 2048; c += 256) {
        int r, ch; u32 dst; const u16* src;
        if (c < 512)       { r = c >> 2; ch = c & 3; dst = st + S13_AH + r * RS + ch * 16; src = Ah + (size_t)r * DIM + k0 + ch * 8; }
        else if (c < 1024) { int i = c - 512;  r = i >> 2; ch = i & 3; dst = st + S13_AL + r * RS + ch * 16; src = Al + (size_t)r * DIM + k0 + ch * 8; }
        else if (c < 1280) { int i = c - 1024; r = i >> 2; ch = i & 3; dst = st + S13_B1H + r * RS + ch * 16; src = g_W1hi + (wbase + r) * DIM + k0 + ch * 8; }
        else if (c < 1536) { int i = c - 1280; r = i >> 2; ch = i & 3; dst = st + S13_B1L + r * RS + ch * 16; src = g_W1lo + (wbase + r) * DIM + k0 + ch * 8; }
        else if (c < 1792) { int i = c - 1536; r = i >> 2; ch = i & 3; dst = st + S13_B3H + r * RS + ch * 16; src = g_W3hi + (wbase + r) * DIM + k0 + ch * 8; }
        else               { int i = c - 1792; r = i >> 2; ch = i & 3; dst = st + S13_B3L + r * RS + ch * 16; src = g_W3lo + (wbase + r) * DIM + k0 + ch * 8; }
        cpa16(dst, src);
    }
}

__global__ __launch_bounds__(256, 1)
void k_gemm13() {
    if ((int)blockIdx.x >= g_ntiles) return;
    extern __shared__ char smraw[];
    u32 sbase = smem_u32(smraw);
    int tid = threadIdx.x, wid = tid >> 5, lane = tid & 31;
    int warpM = wid >> 1, warpN = wid & 1;
    int e = g_tile_expert[blockIdx.x], row0 = g_tile_row0[blockIdx.x];
    int n0w = blockIdx.y * 64;

    const u16* Ah = g_Xhi + (size_t)row0 * DIM;
    const u16* Al = g_Xlo + (size_t)row0 * DIM;
    size_t wbase = (size_t)e * HID + n0w;

    // ldmatrix lane offsets
    u32 aoff = (u32)((lane & 15) * RS + (lane >> 4) * 16);
    u32 boff = (u32)((lane & 7) * RS + ((lane >> 3) & 1) * 16);
    u32 aW = (u32)(warpM * 32 * RS);
    u32 bW = (u32)(warpN * 32 * RS);

    float acc1[2][4][4], acc3[2][4][4];
#pragma unroll
    for (int mt = 0; mt < 2; mt++)
#pragma unroll
        for (int nt = 0; nt < 4; nt++)
#pragma unroll
            for (int j = 0; j < 4; j++) { acc1[mt][nt][j] = 0.f; acc3[mt][nt][j] = 0.f; }

    const int KT = DIM / 32;  // 32
    load13(sbase, 0, 0, Ah, Al, wbase, tid); cpa_commit();
    load13(sbase, 1, 1, Ah, Al, wbase, tid); cpa_commit();
    load13(sbase, 2, 2, Ah, Al, wbase, tid); cpa_commit();

    for (int kt = 0; kt < KT; kt++) {
        int stage = kt % 3;
        u32 st = sbase + stage * SS13;
        cpa_wait2();
        __syncthreads();
#pragma unroll
        for (int kh = 0; kh < 2; kh++) {
            u32 AH[2][4], AL[2][4];
#pragma unroll
            for (int mt = 0; mt < 2; mt++) {
                ldsm4(AH[mt], st + S13_AH + aW + mt * 16 * RS + kh * 32 + aoff);
                ldsm4(AL[mt], st + S13_AL + aW + mt * 16 * RS + kh * 32 + aoff);
            }
#pragma unroll
            for (int nt = 0; nt < 4; nt++) {
                u32 nb = bW + nt * 8 * RS + kh * 32 + boff;
                u32 b1h[2], b1l[2], b3h[2], b3l[2];
                ldsm2(b1h, st + S13_B1H + nb);
                ldsm2(b1l, st + S13_B1L + nb);
                ldsm2(b3h, st + S13_B3H + nb);
                ldsm2(b3l, st + S13_B3L + nb);
#pragma unroll
                for (int mt = 0; mt < 2; mt++) {
                    mma16816(acc1[mt][nt], AH[mt], b1h);
                    mma16816(acc1[mt][nt], AH[mt], b1l);
                    mma16816(acc1[mt][nt], AL[mt], b1h);
                    mma16816(acc3[mt][nt], AH[mt], b3h);
                    mma16816(acc3[mt][nt], AH[mt], b3l);
                    mma16816(acc3[mt][nt], AL[mt], b3h);
                }
            }
        }
        __syncthreads();
        if (kt + 3 < KT) load13(sbase, stage, kt + 3, Ah, Al, wbase, tid);
        cpa_commit();
    }

    int g4 = lane >> 2, t4 = lane & 3;
#pragma unroll
    for (int mt = 0; mt < 2; mt++) {
        int rA = row0 + warpM * 32 + mt * 16 + g4;
#pragma unroll
        for (int nt = 0; nt < 4; nt++) {
            int col = n0w + warpN * 32 + nt * 8 + t4 * 2;
            const float* d1 = acc1[mt][nt];
            const float* d3 = acc3[mt][nt];
#pragma unroll
            for (int half = 0; half < 2; half++) {
                int row = rA + half * 8;
                float r0 = fmaxf(d1[half * 2], 0.f), r1 = fmaxf(d1[half * 2 + 1], 0.f);
                float h0 = r0 * r0 * d3[half * 2];
                float h1 = r1 * r1 * d3[half * 2 + 1];
                u16 hh0 = f2bf(h0), hh1 = f2bf(h1);
                u16 ll0 = f2bf(h0 - bf2f(hh0)), ll1 = f2bf(h1 - bf2f(hh1));
                *(u32*)(g_Hhi + (size_t)row * HID + col) = pk(hh0, hh1);
                *(u32*)(g_Hlo + (size_t)row * HID + col) = pk(ll0, ll1);
            }
        }
    }
}

// ---------------- GEMM2: O = coef * (H W2^T) ----------------
#define S2_AH 0
#define S2_AL 10240
#define S2_BH 20480
#define S2_BL 25600
#define SS2 30720
#define SMEM2 (3 * SS2)

__device__ __forceinline__ void load2(u32 sbase, int stage, int kt,
                                      const u16* Ah, const u16* Al,
                                      size_t wbase, int tid) {
    int k0 = kt * 32;
    u32 st = sbase + stage * SS2;
    for (int c = tid; c < 1536; c += 256) {
        int r, ch; u32 dst; const u16* src;
        if (c < 512)       { r = c >> 2; ch = c & 3; dst = st + S2_AH + r * RS + ch * 16; src = Ah + (size_t)r * HID + k0 + ch * 8; }
        else if (c < 1024) { int i = c - 512;  r = i >> 2; ch = i & 3; dst = st + S2_AL + r * RS + ch * 16; src = Al + (size_t)r * HID + k0 + ch * 8; }
        else if (c < 1280) { int i = c - 1024; r = i >> 2; ch = i & 3; dst = st + S2_BH + r * RS + ch * 16; src = g_W2hi + (wbase + r) * HID + k0 + ch * 8; }
        else               { int i = c - 1280; r = i >> 2; ch = i & 3; dst = st + S2_BL + r * RS + ch * 16; src = g_W2lo + (wbase + r) * HID + k0 + ch * 8; }
        cpa16(dst, src);
    }
}

__global__ __launch_bounds__(256, 1)
void k_gemm2() {
    if ((int)blockIdx.x >= g_ntiles) return;
    extern __shared__ char smraw[];
    u32 sbase = smem_u32(smraw);
    int tid = threadIdx.x, wid = tid >> 5, lane = tid & 31;
    int warpM = wid >> 1, warpN = wid & 1;
    int e = g_tile_expert[blockIdx.x], row0 = g_tile_row0[blockIdx.x];
    int n0w = blockIdx.y * 64;

    const u16* Ah = g_Hhi + (size_t)row0 * HID;
    const u16* Al = g_Hlo + (size_t)row0 * HID;
    size_t wbase = (size_t)e * DIM + n0w;

    u32 aoff = (u32)((lane & 15) * RS + (lane >> 4) * 16);
    u32 boff = (u32)((lane & 7) * RS + ((lane >> 3) & 1) * 16);
    u32 aW = (u32)(warpM * 32 * RS);
    u32 bW = (u32)(warpN * 32 * RS);

    float acc[2][4][4];
#pragma unroll
    for (int mt = 0; mt < 2; mt++)
#pragma unroll
        for (int nt = 0; nt < 4; nt++)
#pragma unroll
            for (int j = 0; j < 4; j++) acc[mt][nt][j] = 0.f;

    const int KT = HID / 32;  // 64
    load2(sbase, 0, 0, Ah, Al, wbase, tid); cpa_commit();
    load2(sbase, 1, 1, Ah, Al, wbase, tid); cpa_commit();
    load2(sbase, 2, 2, Ah, Al, wbase, tid); cpa_commit();

    for (int kt = 0; kt < KT; kt++) {
        int stage = kt % 3;
        u32 st = sbase + stage * SS2;
        cpa_wait2();
        __syncthreads();
#pragma unroll
        for (int kh = 0; kh < 2; kh++) {
            u32 AH[2][4], AL[2][4];
#pragma unroll
            for (int mt = 0; mt < 2; mt++) {
                ldsm4(AH[mt], st + S2_AH + aW + mt * 16 * RS + kh * 32 + aoff);
                ldsm4(AL[mt], st + S2_AL + aW + mt * 16 * RS + kh * 32 + aoff);
            }
#pragma unroll
            for (int nt = 0; nt < 4; nt++) {
                u32 nb = bW + nt * 8 * RS + kh * 32 + boff;
                u32 bh[2], bl[2];
                ldsm2(bh, st + S2_BH + nb);
                ldsm2(bl, st + S2_BL + nb);
#pragma unroll
                for (int mt = 0; mt < 2; mt++) {
                    mma16816(acc[mt][nt], AH[mt], bh);
                    mma16816(acc[mt][nt], AH[mt], bl);
                    mma16816(acc[mt][nt], AL[mt], bh);
                }
            }
        }
        __syncthreads();
        if (kt + 3 < KT) load2(sbase, stage, kt + 3, Ah, Al, wbase, tid);
        cpa_commit();
    }

    int g4 = lane >> 2, t4 = lane & 3;
#pragma unroll
    for (int mt = 0; mt < 2; mt++) {
        int rA = row0 + warpM * 32 + mt * 16 + g4;
        float c0 = g_row_coef[rA], c1 = g_row_coef[rA + 8];
#pragma unroll
        for (int nt = 0; nt < 4; nt++) {
            int col = n0w + warpN * 32 + nt * 8 + t4 * 2;
            const float* d = acc[mt][nt];
            float2 v0 = make_float2(c0 * d[0], c0 * d[1]);
            float2 v1 = make_float2(c1 * d[2], c1 * d[3]);
            *(float2*)(g_Orows + (size_t)rA * DIM + col) = v0;
            *(float2*)(g_Orows + (size_t)(rA + 8) * DIM + col) = v1;
        }
    }
}

__global__ void k_combine(float* __restrict__ out) {
    int t = blockIdx.x;
    int i = threadIdx.x * 4;
    int r0 = g_token_row[2 * t], r1 = g_token_row[2 * t + 1];
    float4 a = *(const float4*)(g_Orows + (size_t)r0 * DIM + i);
    float4 b = *(const float4*)(g_Orows + (size_t)r1 * DIM + i);
    *(float4*)(out + (size_t)t * DIM + i) =
        make_float4(a.x + b.x, a.y + b.y, a.z + b.z, a.w + b.w);
}

extern "C" void kernel_launch(void* const* d_in, const int* in_sizes, int n_in,
                              void* d_out, int out_size) {
    const float* x  = (const float*)d_in[0];
    const float* W1 = (const float*)d_in[1];
    const float* W2 = (const float*)d_in[2];
    const float* W3 = (const float*)d_in[3];
    const float* gw = (const float*)d_in[4];
    const float* gb = (const float*)d_in[5];
    float* out = (float*)d_out;

    cudaFuncSetAttribute(k_gemm13, cudaFuncAttributeMaxDynamicSharedMemorySize, SMEM13);
    cudaFuncSetAttribute(k_gemm2,  cudaFuncAttributeMaxDynamicSharedMemorySize, SMEM2);

    k_init<<<68, 256>>>();
    k_split<<<16384, 256>>>(W1, 0);
    k_split<<<16384, 256>>>(W3, 1);
    k_split<<<16384, 256>>>(W2, 2);
    k_gate<<<1024, 256>>>(x, gw, gb);
    k_offsets<<<1, 1>>>();
    k_assign<<<32, 256>>>();
    k_gather<<<MAXROWS, 256>>>(x);
    k_gemm13<<<dim3(MAXMT, HID / 64), 256, SMEM13>>>();
    k_gemm2<<<dim3(MAXMT, DIM / 64), 256, SMEM2>>>();
    k_combine<<<NTOK, 256>>>(out);
}

// round 4
// speedup vs baseline: 1.3283x; 1.3283x over previous
#include <cuda_runtime.h>
#include <cuda_fp16.h>
#include <cstdint>

typedef unsigned short u16;
typedef unsigned int   u32;
typedef unsigned long long u64;

#define NTOK 8192
#define DIM  1024
#define HID  2048
#define NE   8
#define MAXROWS 17408
#define MAXMT 136

__device__ int   g_counts[NE], g_fill[NE], g_seg[NE + 1], g_ntiles;
__device__ int   g_tile_expert[MAXMT], g_tile_row0[MAXMT];
__device__ int   g_row_token[MAXROWS];
__device__ float g_row_coef[MAXROWS];
__device__ int   g_token_row[NTOK * 2];
__device__ int   g_tok_e[NTOK * 2];
__device__ float g_tok_p[NTOK * 2];

__device__ __align__(16) u16 g_Xhi[(size_t)MAXROWS * DIM];
__device__ __align__(16) u16 g_Xlo[(size_t)MAXROWS * DIM];
__device__ __align__(16) u16 g_W1hi[(size_t)NE * HID * DIM];
__device__ __align__(16) u16 g_W1lo[(size_t)NE * HID * DIM];
__device__ __align__(16) u16 g_W3hi[(size_t)NE * HID * DIM];
__device__ __align__(16) u16 g_W2hi[(size_t)NE * DIM * HID];
__device__ __align__(16) u16 g_Hhi[(size_t)MAXROWS * HID];
__device__ __align__(16) u16 g_Hlo[(size_t)MAXROWS * HID];
__device__ __align__(16) float g_Orows[(size_t)MAXROWS * DIM];

__device__ __forceinline__ u16 f2h(float f) { return __half_as_ushort(__float2half_rn(f)); }
__device__ __forceinline__ float h2f(u16 u) { return __half2float(__ushort_as_half(u)); }
__device__ __forceinline__ u32 pk(u16 a, u16 b) { return (u32)a | ((u32)b << 16); }

__device__ __forceinline__ u32 smem_u32(const void* p) {
    u32 a;
    asm("{ .reg .u64 t; cvta.to.shared.u64 t, %1; cvt.u32.u64 %0, t; }" : "=r"(a) : "l"(p));
    return a;
}
__device__ __forceinline__ void cpa16(u32 dst, const void* src) {
    asm volatile("cp.async.cg.shared.global [%0], [%1], 16;" :: "r"(dst), "l"(src) : "memory");
}
__device__ __forceinline__ void cpa_commit() { asm volatile("cp.async.commit_group;" ::: "memory"); }
__device__ __forceinline__ void cpa_wait2() { asm volatile("cp.async.wait_group 2;" ::: "memory"); }

__device__ __forceinline__ void ldsm4(u32* r, u32 addr) {
    asm volatile("ldmatrix.sync.aligned.m8n8.x4.shared.b16 {%0,%1,%2,%3}, [%4];"
                 : "=r"(r[0]), "=r"(r[1]), "=r"(r[2]), "=r"(r[3]) : "r"(addr));
}
__device__ __forceinline__ void ldsm2(u32* r, u32 addr) {
    asm volatile("ldmatrix.sync.aligned.m8n8.x2.shared.b16 {%0,%1}, [%2];"
                 : "=r"(r[0]), "=r"(r[1]) : "r"(addr));
}
__device__ __forceinline__ void mma16816(float* c, const u32* a, const u32* b) {
    asm volatile(
        "mma.sync.aligned.m16n8k16.row.col.f32.f16.f16.f32 "
        "{%0,%1,%2,%3}, {%4,%5,%6,%7}, {%8,%9}, {%0,%1,%2,%3};"
        : "+f"(c[0]), "+f"(c[1]), "+f"(c[2]), "+f"(c[3])
        : "r"(a[0]), "r"(a[1]), "r"(a[2]), "r"(a[3]), "r"(b[0]), "r"(b[1]));
}

// ---------------- fused prep: init + weight splits (one launch) ----------------
// blocks [0, 16384): W1 -> hi+lo ; [16384, 32768): W3 -> hi ; [32768, 49152): W2 -> hi
__global__ void k_prep(const float* __restrict__ W1, const float* __restrict__ W2,
                       const float* __restrict__ W3) {
    int b = blockIdx.x;
    if (b < 68) {
        int i = b * 256 + threadIdx.x;
        if (i < MAXROWS) { g_row_token[i] = -1; g_row_coef[i] = 0.f; }
        if (i < NE) { g_counts[i] = 0; g_fill[i] = 0; }
    }
    int which = b >> 14;
    size_t i = ((size_t)(b & 16383) * 256 + threadIdx.x) * 4;
    if (which == 0) {
        float4 v = *(const float4*)(W1 + i);
        u16 h0 = f2h(v.x), h1 = f2h(v.y), h2 = f2h(v.z), h3 = f2h(v.w);
        u16 l0 = f2h(v.x - h2f(h0)), l1 = f2h(v.y - h2f(h1));
        u16 l2 = f2h(v.z - h2f(h2)), l3 = f2h(v.w - h2f(h3));
        *(uint2*)(g_W1hi + i) = make_uint2(pk(h0, h1), pk(h2, h3));
        *(uint2*)(g_W1lo + i) = make_uint2(pk(l0, l1), pk(l2, l3));
    } else if (which == 1) {
        float4 v = *(const float4*)(W3 + i);
        *(uint2*)(g_W3hi + i) = make_uint2(pk(f2h(v.x), f2h(v.y)), pk(f2h(v.z), f2h(v.w)));
    } else {
        float4 v = *(const float4*)(W2 + i);
        *(uint2*)(g_W2hi + i) = make_uint2(pk(f2h(v.x), f2h(v.y)), pk(f2h(v.z), f2h(v.w)));
    }
}

__global__ void k_gate(const float* __restrict__ x, const float* __restrict__ gw,
                       const float* __restrict__ gb) {
    int w = (blockIdx.x * blockDim.x + threadIdx.x) >> 5;
    int lane = threadIdx.x & 31;
    if (w >= NTOK) return;
    const float* xr = x + (size_t)w * DIM;
    float acc[NE];
#pragma unroll
    for (int e = 0; e < NE; e++) acc[e] = 0.f;
    for (int j = lane; j < DIM; j += 32) {
        float xv = xr[j];
#pragma unroll
        for (int e = 0; e < NE; e++) acc[e] = fmaf(xv, gw[e * DIM + j], acc[e]);
    }
#pragma unroll
    for (int e = 0; e < NE; e++)
#pragma unroll
        for (int o = 16; o; o >>= 1) acc[e] += __shfl_xor_sync(0xffffffffu, acc[e], o);
    if (lane == 0) {
#pragma unroll
        for (int e = 0; e < NE; e++) acc[e] += gb[e];
        int e0 = 0;
#pragma unroll
        for (int e = 1; e < NE; e++) if (acc[e] > acc[e0]) e0 = e;
        int e1 = (e0 == 0) ? 1 : 0;
#pragma unroll
        for (int e = 0; e < NE; e++) if (e != e0 && acc[e] > acc[e1]) e1 = e;
        float p0 = 1.f / (1.f + expf(acc[e1] - acc[e0]));
        g_tok_e[2 * w] = e0; g_tok_e[2 * w + 1] = e1;
        g_tok_p[2 * w] = p0; g_tok_p[2 * w + 1] = 1.f - p0;
        atomicAdd(&g_counts[e0], 1);
        atomicAdd(&g_counts[e1], 1);
    }
}

__global__ void k_offsets() {
    int off = 0, nt = 0;
    for (int e = 0; e < NE; e++) {
        g_seg[e] = off;
        int t = (g_counts[e] + 127) >> 7;
        for (int m = 0; m < t; m++) { g_tile_expert[nt] = e; g_tile_row0[nt] = off + (m << 7); nt++; }
        off += t << 7;
    }
    g_seg[NE] = off;
    g_ntiles = nt;
}

__global__ void k_assign() {
    int t = blockIdx.x * 256 + threadIdx.x;
    if (t >= NTOK) return;
#pragma unroll
    for (int k = 0; k < 2; k++) {
        int e = g_tok_e[2 * t + k];
        int row = g_seg[e] + atomicAdd(&g_fill[e], 1);
        g_row_token[row] = t;
        g_row_coef[row] = g_tok_p[2 * t + k];
        g_token_row[2 * t + k] = row;
    }
}

__global__ void k_gather(const float* __restrict__ x) {
    int row = blockIdx.x;
    int t = g_row_token[row];
    size_t off = (size_t)row * DIM + threadIdx.x * 4;
    float4 v = make_float4(0.f, 0.f, 0.f, 0.f);
    if (t >= 0) v = *(const float4*)(x + (size_t)t * DIM + threadIdx.x * 4);
    u16 h0 = f2h(v.x), h1 = f2h(v.y), h2 = f2h(v.z), h3 = f2h(v.w);
    u16 l0 = f2h(v.x - h2f(h0)), l1 = f2h(v.y - h2f(h1));
    u16 l2 = f2h(v.z - h2f(h2)), l3 = f2h(v.w - h2f(h3));
    *(uint2*)(g_Xhi + off) = make_uint2(pk(h0, h1), pk(h2, h3));
    *(uint2*)(g_Xlo + off) = make_uint2(pk(l0, l1), pk(l2, l3));
}

// ---------------- GEMM13: H = relu(X W1^T)^2 * (X W3^T) ----------------
// CTA 128(M) x 64(N), BK=32, 3-stage cp.async, rows padded to 80B.
#define RS 80
#define S13_AH 0
#define S13_AL 10240
#define S13_B1H 20480
#define S13_B1L 25600
#define S13_B3H 30720
#define SS13 35840
#define SMEM13 (3 * SS13)

__device__ __forceinline__ void load13(u32 sbase, int stage, int kt,
                                       const u16* Ah, const u16* Al,
                                       size_t wbase, int tid) {
    int k0 = kt * 32;
    u32 st = sbase + stage * SS13;
    for (int c = tid; c < 1792; c += 256) {
        int r, ch; u32 dst; const u16* src;
        if (c < 512)       { r = c >> 2; ch = c & 3; dst = st + S13_AH + r * RS + ch * 16; src = Ah + (size_t)r * DIM + k0 + ch * 8; }
        else if (c < 1024) { int i = c - 512;  r = i >> 2; ch = i & 3; dst = st + S13_AL + r * RS + ch * 16; src = Al + (size_t)r * DIM + k0 + ch * 8; }
        else if (c < 1280) { int i = c - 1024; r = i >> 2; ch = i & 3; dst = st + S13_B1H + r * RS + ch * 16; src = g_W1hi + (wbase + r) * DIM + k0 + ch * 8; }
        else if (c < 1536) { int i = c - 1280; r = i >> 2; ch = i & 3; dst = st + S13_B1L + r * RS + ch * 16; src = g_W1lo + (wbase + r) * DIM + k0 + ch * 8; }
        else               { int i = c - 1536; r = i >> 2; ch = i & 3; dst = st + S13_B3H + r * RS + ch * 16; src = g_W3hi + (wbase + r) * DIM + k0 + ch * 8; }
        cpa16(dst, src);
    }
}

__global__ __launch_bounds__(256, 1)
void k_gemm13() {
    if ((int)blockIdx.x >= g_ntiles) return;
    extern __shared__ char smraw[];
    u32 sbase = smem_u32(smraw);
    int tid = threadIdx.x, wid = tid >> 5, lane = tid & 31;
    int warpM = wid >> 1, warpN = wid & 1;
    int e = g_tile_expert[blockIdx.x], row0 = g_tile_row0[blockIdx.x];
    int n0w = blockIdx.y * 64;

    const u16* Ah = g_Xhi + (size_t)row0 * DIM;
    const u16* Al = g_Xlo + (size_t)row0 * DIM;
    size_t wbase = (size_t)e * HID + n0w;

    u32 aoff = (u32)((lane & 15) * RS + (lane >> 4) * 16);
    u32 boff = (u32)((lane & 7) * RS + ((lane >> 3) & 1) * 16);
    u32 aW = (u32)(warpM * 32 * RS);
    u32 bW = (u32)(warpN * 32 * RS);

    float acc1[2][4][4], acc3[2][4][4];
#pragma unroll
    for (int mt = 0; mt < 2; mt++)
#pragma unroll
        for (int nt = 0; nt < 4; nt++)
#pragma unroll
            for (int j = 0; j < 4; j++) { acc1[mt][nt][j] = 0.f; acc3[mt][nt][j] = 0.f; }

    const int KT = DIM / 32;
    load13(sbase, 0, 0, Ah, Al, wbase, tid); cpa_commit();
    load13(sbase, 1, 1, Ah, Al, wbase, tid); cpa_commit();
    load13(sbase, 2, 2, Ah, Al, wbase, tid); cpa_commit();

    for (int kt = 0; kt < KT; kt++) {
        int stage = kt % 3;
        u32 st = sbase + stage * SS13;
        cpa_wait2();
        __syncthreads();
#pragma unroll
        for (int kh = 0; kh < 2; kh++) {
            u32 AH[2][4], AL[2][4];
#pragma unroll
            for (int mt = 0; mt < 2; mt++) {
                ldsm4(AH[mt], st + S13_AH + aW + mt * 16 * RS + kh * 32 + aoff);
                ldsm4(AL[mt], st + S13_AL + aW + mt * 16 * RS + kh * 32 + aoff);
            }
#pragma unroll
            for (int nt = 0; nt < 4; nt++) {
                u32 nb = bW + nt * 8 * RS + kh * 32 + boff;
                u32 b1h[2], b1l[2], b3h[2];
                ldsm2(b1h, st + S13_B1H + nb);
                ldsm2(b1l, st + S13_B1L + nb);
                ldsm2(b3h, st + S13_B3H + nb);
#pragma unroll
                for (int mt = 0; mt < 2; mt++) {
                    mma16816(acc1[mt][nt], AH[mt], b1h);
                    mma16816(acc1[mt][nt], AH[mt], b1l);
                    mma16816(acc1[mt][nt], AL[mt], b1h);
                    mma16816(acc3[mt][nt], AH[mt], b3h);
                    mma16816(acc3[mt][nt], AL[mt], b3h);
                }
            }
        }
        __syncthreads();
        if (kt + 3 < KT) load13(sbase, stage, kt + 3, Ah, Al, wbase, tid);
        cpa_commit();
    }

    int g4 = lane >> 2, t4 = lane & 3;
#pragma unroll
    for (int mt = 0; mt < 2; mt++) {
        int rA = row0 + warpM * 32 + mt * 16 + g4;
#pragma unroll
        for (int nt = 0; nt < 4; nt++) {
            int col = n0w + warpN * 32 + nt * 8 + t4 * 2;
            const float* d1 = acc1[mt][nt];
            const float* d3 = acc3[mt][nt];
#pragma unroll
            for (int half = 0; half < 2; half++) {
                int row = rA + half * 8;
                float r0 = fmaxf(d1[half * 2], 0.f), r1 = fmaxf(d1[half * 2 + 1], 0.f);
                float h0 = r0 * r0 * d3[half * 2];
                float h1 = r1 * r1 * d3[half * 2 + 1];
                u16 hh0 = f2h(h0), hh1 = f2h(h1);
                u16 ll0 = f2h(h0 - h2f(hh0)), ll1 = f2h(h1 - h2f(hh1));
                *(u32*)(g_Hhi + (size_t)row * HID + col) = pk(hh0, hh1);
                *(u32*)(g_Hlo + (size_t)row * HID + col) = pk(ll0, ll1);
            }
        }
    }
}

// ---------------- GEMM2: O = coef * (H W2^T) ----------------
#define S2_AH 0
#define S2_AL 10240
#define S2_BH 20480
#define SS2 25600
#define SMEM2 (3 * SS2)

__device__ __forceinline__ void load2(u32 sbase, int stage, int kt,
                                      const u16* Ah, const u16* Al,
                                      size_t wbase, int tid) {
    int k0 = kt * 32;
    u32 st = sbase + stage * SS2;
    for (int c = tid; c < 1280; c += 256) {
        int r, ch; u32 dst; const u16* src;
        if (c < 512)       { r = c >> 2; ch = c & 3; dst = st + S2_AH + r * RS + ch * 16; src = Ah + (size_t)r * HID + k0 + ch * 8; }
        else if (c < 1024) { int i = c - 512;  r = i >> 2; ch = i & 3; dst = st + S2_AL + r * RS + ch * 16; src = Al + (size_t)r * HID + k0 + ch * 8; }
        else               { int i = c - 1024; r = i >> 2; ch = i & 3; dst = st + S2_BH + r * RS + ch * 16; src = g_W2hi + (wbase + r) * HID + k0 + ch * 8; }
        cpa16(dst, src);
    }
}

__global__ __launch_bounds__(256, 1)
void k_gemm2() {
    if ((int)blockIdx.x >= g_ntiles) return;
    extern __shared__ char smraw[];
    u32 sbase = smem_u32(smraw);
    int tid = threadIdx.x, wid = tid >> 5, lane = tid & 31;
    int warpM = wid >> 1, warpN = wid & 1;
    int e = g_tile_expert[blockIdx.x], row0 = g_tile_row0[blockIdx.x];
    int n0w = blockIdx.y * 64;

    const u16* Ah = g_Hhi + (size_t)row0 * HID;
    const u16* Al = g_Hlo + (size_t)row0 * HID;
    size_t wbase = (size_t)e * DIM + n0w;

    u32 aoff = (u32)((lane & 15) * RS + (lane >> 4) * 16);
    u32 boff = (u32)((lane & 7) * RS + ((lane >> 3) & 1) * 16);
    u32 aW = (u32)(warpM * 32 * RS);
    u32 bW = (u32)(warpN * 32 * RS);

    float acc[2][4][4];
#pragma unroll
    for (int mt = 0; mt < 2; mt++)
#pragma unroll
        for (int nt = 0; nt < 4; nt++)
#pragma unroll
            for (int j = 0; j < 4; j++) acc[mt][nt][j] = 0.f;

    const int KT = HID / 32;
    load2(sbase, 0, 0, Ah, Al, wbase, tid); cpa_commit();
    load2(sbase, 1, 1, Ah, Al, wbase, tid); cpa_commit();
    load2(sbase, 2, 2, Ah, Al, wbase, tid); cpa_commit();

    for (int kt = 0; kt < KT; kt++) {
        int stage = kt % 3;
        u32 st = sbase + stage * SS2;
        cpa_wait2();
        __syncthreads();
#pragma unroll
        for (int kh = 0; kh < 2; kh++) {
            u32 AH[2][4], AL[2][4];
#pragma unroll
            for (int mt = 0; mt < 2; mt++) {
                ldsm4(AH[mt], st + S2_AH + aW + mt * 16 * RS + kh * 32 + aoff);
                ldsm4(AL[mt], st + S2_AL + aW + mt * 16 * RS + kh * 32 + aoff);
            }
#pragma unroll
            for (int nt = 0; nt < 4; nt++) {
                u32 nb = bW + nt * 8 * RS + kh * 32 + boff;
                u32 bh[2];
                ldsm2(bh, st + S2_BH + nb);
#pragma unroll
                for (int mt = 0; mt < 2; mt++) {
                    mma16816(acc[mt][nt], AH[mt], bh);
                    mma16816(acc[mt][nt], AL[mt], bh);
                }
            }
        }
        __syncthreads();
        if (kt + 3 < KT) load2(sbase, stage, kt + 3, Ah, Al, wbase, tid);
        cpa_commit();
    }

    int g4 = lane >> 2, t4 = lane & 3;
#pragma unroll
    for (int mt = 0; mt < 2; mt++) {
        int rA = row0 + warpM * 32 + mt * 16 + g4;
        float c0 = g_row_coef[rA], c1 = g_row_coef[rA + 8];
#pragma unroll
        for (int nt = 0; nt < 4; nt++) {
            int col = n0w + warpN * 32 + nt * 8 + t4 * 2;
            const float* d = acc[mt][nt];
            *(float2*)(g_Orows + (size_t)rA * DIM + col) = make_float2(c0 * d[0], c0 * d[1]);
            *(float2*)(g_Orows + (size_t)(rA + 8) * DIM + col) = make_float2(c1 * d[2], c1 * d[3]);
        }
    }
}

__global__ void k_combine(float* __restrict__ out) {
    int t = blockIdx.x;
    int i = threadIdx.x * 4;
    int r0 = g_token_row[2 * t], r1 = g_token_row[2 * t + 1];
    float4 a = *(const float4*)(g_Orows + (size_t)r0 * DIM + i);
    float4 b = *(const float4*)(g_Orows + (size_t)r1 * DIM + i);
    *(float4*)(out + (size_t)t * DIM + i) =
        make_float4(a.x + b.x, a.y + b.y, a.z + b.z, a.w + b.w);
}

extern "C" void kernel_launch(void* const* d_in, const int* in_sizes, int n_in,
                              void* d_out, int out_size) {
    const float* x  = (const float*)d_in[0];
    const float* W1 = (const float*)d_in[1];
    const float* W2 = (const float*)d_in[2];
    const float* W3 = (const float*)d_in[3];
    const float* gw = (const float*)d_in[4];
    const float* gb = (const float*)d_in[5];
    float* out = (float*)d_out;

    cudaFuncSetAttribute(k_gemm13, cudaFuncAttributeMaxDynamicSharedMemorySize, SMEM13);
    cudaFuncSetAttribute(k_gemm2,  cudaFuncAttributeMaxDynamicSharedMemorySize, SMEM2);

    k_prep<<<49152, 256>>>(W1, W2, W3);
    k_gate<<<1024, 256>>>(x, gw, gb);
    k_offsets<<<1, 1>>>();
    k_assign<<<32, 256>>>();
    k_gather<<<MAXROWS, 256>>>(x);
    k_gemm13<<<dim3(MAXMT, HID / 64), 256, SMEM13>>>();
    k_gemm2<<<dim3(MAXMT, DIM / 64), 256, SMEM2>>>();
    k_combine<<<NTOK, 256>>>(out);
}

// round 5
// speedup vs baseline: 1.7335x; 1.3051x over previous
#include <cuda_runtime.h>
#include <cuda_fp16.h>
#include <cstdint>

typedef unsigned short u16;
typedef unsigned int   u32;
typedef unsigned long long u64;

#define NTOK 8192
#define DIM  1024
#define HID  2048
#define NE   8
#define MAXROWS 17408
#define MAXMT 136

__device__ int   g_counts[NE], g_fill[NE], g_seg[NE + 1], g_ntiles;
__device__ int   g_tile_expert[MAXMT], g_tile_row0[MAXMT];
__device__ int   g_row_token[MAXROWS];
__device__ float g_row_coef[MAXROWS];
__device__ int   g_token_row[NTOK * 2];
__device__ int   g_tok_e[NTOK * 2];
__device__ float g_tok_p[NTOK * 2];

__device__ __align__(16) u16 g_Xhi[(size_t)MAXROWS * DIM];
__device__ __align__(16) u16 g_Xlo[(size_t)MAXROWS * DIM];
__device__ __align__(16) u16 g_W1hi[(size_t)NE * HID * DIM];
__device__ __align__(16) u16 g_W3hi[(size_t)NE * HID * DIM];
__device__ __align__(16) u16 g_W2hi[(size_t)NE * DIM * HID];
__device__ __align__(16) u16 g_Hhi[(size_t)MAXROWS * HID];
__device__ __align__(16) u16 g_Hlo[(size_t)MAXROWS * HID];
__device__ __align__(16) float g_Orows[(size_t)MAXROWS * DIM];

__device__ __forceinline__ u16 f2h(float f) { return __half_as_ushort(__float2half_rn(f)); }
__device__ __forceinline__ float h2f(u16 u) { return __half2float(__ushort_as_half(u)); }
__device__ __forceinline__ u32 pk(u16 a, u16 b) { return (u32)a | ((u32)b << 16); }

__device__ __forceinline__ u32 smem_u32(const void* p) {
    u32 a;
    asm("{ .reg .u64 t; cvta.to.shared.u64 t, %1; cvt.u32.u64 %0, t; }" : "=r"(a) : "l"(p));
    return a;
}
__device__ __forceinline__ void cpa16(u32 dst, const void* src) {
    asm volatile("cp.async.cg.shared.global [%0], [%1], 16;" :: "r"(dst), "l"(src) : "memory");
}
__device__ __forceinline__ void cpa_commit() { asm volatile("cp.async.commit_group;" ::: "memory"); }
__device__ __forceinline__ void cpa_wait2() { asm volatile("cp.async.wait_group 2;" ::: "memory"); }

__device__ __forceinline__ void ldsm4(u32* r, u32 addr) {
    asm volatile("ldmatrix.sync.aligned.m8n8.x4.shared.b16 {%0,%1,%2,%3}, [%4];"
                 : "=r"(r[0]), "=r"(r[1]), "=r"(r[2]), "=r"(r[3]) : "r"(addr));
}
__device__ __forceinline__ void ldsm2(u32* r, u32 addr) {
    asm volatile("ldmatrix.sync.aligned.m8n8.x2.shared.b16 {%0,%1}, [%2];"
                 : "=r"(r[0]), "=r"(r[1]) : "r"(addr));
}
__device__ __forceinline__ void mma16816(float* c, const u32* a, const u32* b) {
    asm volatile(
        "mma.sync.aligned.m16n8k16.row.col.f32.f16.f16.f32 "
        "{%0,%1,%2,%3}, {%4,%5,%6,%7}, {%8,%9}, {%0,%1,%2,%3};"
        : "+f"(c[0]), "+f"(c[1]), "+f"(c[2]), "+f"(c[3])
        : "r"(a[0]), "r"(a[1]), "r"(a[2]), "r"(a[3]), "r"(b[0]), "r"(b[1]));
}

// ---------------- fused prep: init + weight fp16 conversion ----------------
__global__ void k_prep(const float* __restrict__ W1, const float* __restrict__ W2,
                       const float* __restrict__ W3) {
    int b = blockIdx.x;
    if (b < 68) {
        int i = b * 256 + threadIdx.x;
        if (i < MAXROWS) { g_row_token[i] = -1; g_row_coef[i] = 0.f; }
        if (i < NE) { g_counts[i] = 0; g_fill[i] = 0; }
    }
    int which = b >> 14;
    size_t i = ((size_t)(b & 16383) * 256 + threadIdx.x) * 4;
    const float* src = (which == 0) ? W1 : (which == 1) ? W3 : W2;
    u16* dst = (which == 0) ? g_W1hi : (which == 1) ? g_W3hi : g_W2hi;
    float4 v = *(const float4*)(src + i);
    *(uint2*)(dst + i) = make_uint2(pk(f2h(v.x), f2h(v.y)), pk(f2h(v.z), f2h(v.w)));
}

__global__ void k_gate(const float* __restrict__ x, const float* __restrict__ gw,
                       const float* __restrict__ gb) {
    int w = (blockIdx.x * blockDim.x + threadIdx.x) >> 5;
    int lane = threadIdx.x & 31;
    if (w >= NTOK) return;
    const float* xr = x + (size_t)w * DIM;
    float acc[NE];
#pragma unroll
    for (int e = 0; e < NE; e++) acc[e] = 0.f;
    for (int j = lane; j < DIM; j += 32) {
        float xv = xr[j];
#pragma unroll
        for (int e = 0; e < NE; e++) acc[e] = fmaf(xv, gw[e * DIM + j], acc[e]);
    }
#pragma unroll
    for (int e = 0; e < NE; e++)
#pragma unroll
        for (int o = 16; o; o >>= 1) acc[e] += __shfl_xor_sync(0xffffffffu, acc[e], o);
    if (lane == 0) {
#pragma unroll
        for (int e = 0; e < NE; e++) acc[e] += gb[e];
        int e0 = 0;
#pragma unroll
        for (int e = 1; e < NE; e++) if (acc[e] > acc[e0]) e0 = e;
        int e1 = (e0 == 0) ? 1 : 0;
#pragma unroll
        for (int e = 0; e < NE; e++) if (e != e0 && acc[e] > acc[e1]) e1 = e;
        float p0 = 1.f / (1.f + expf(acc[e1] - acc[e0]));
        g_tok_e[2 * w] = e0; g_tok_e[2 * w + 1] = e1;
        g_tok_p[2 * w] = p0; g_tok_p[2 * w + 1] = 1.f - p0;
        atomicAdd(&g_counts[e0], 1);
        atomicAdd(&g_counts[e1], 1);
    }
}

__global__ void k_offsets() {
    int off = 0, nt = 0;
    for (int e = 0; e < NE; e++) {
        g_seg[e] = off;
        int t = (g_counts[e] + 127) >> 7;
        for (int m = 0; m < t; m++) { g_tile_expert[nt] = e; g_tile_row0[nt] = off + (m << 7); nt++; }
        off += t << 7;
    }
    g_seg[NE] = off;
    g_ntiles = nt;
}

__global__ void k_assign() {
    int t = blockIdx.x * 256 + threadIdx.x;
    if (t >= NTOK) return;
#pragma unroll
    for (int k = 0; k < 2; k++) {
        int e = g_tok_e[2 * t + k];
        int row = g_seg[e] + atomicAdd(&g_fill[e], 1);
        g_row_token[row] = t;
        g_row_coef[row] = g_tok_p[2 * t + k];
        g_token_row[2 * t + k] = row;
    }
}

__global__ void k_gather(const float* __restrict__ x) {
    int row = blockIdx.x;
    int t = g_row_token[row];
    size_t off = (size_t)row * DIM + threadIdx.x * 4;
    float4 v = make_float4(0.f, 0.f, 0.f, 0.f);
    if (t >= 0) v = *(const float4*)(x + (size_t)t * DIM + threadIdx.x * 4);
    u16 h0 = f2h(v.x), h1 = f2h(v.y), h2 = f2h(v.z), h3 = f2h(v.w);
    u16 l0 = f2h(v.x - h2f(h0)), l1 = f2h(v.y - h2f(h1));
    u16 l2 = f2h(v.z - h2f(h2)), l3 = f2h(v.w - h2f(h3));
    *(uint2*)(g_Xhi + off) = make_uint2(pk(h0, h1), pk(h2, h3));
    *(uint2*)(g_Xlo + off) = make_uint2(pk(l0, l1), pk(l2, l3));
}

// ---------------- GEMM13: H = relu(X W1^T)^2 * (X W3^T) ----------------
// CTA 128(M) x 128(N), BK=32, 3-stage cp.async, rows padded to 80B.
// Warp tile 32(M) x 64(N); 8 warps = 4(M) x 2(N).
#define RS 80
#define S13_AH 0
#define S13_AL 10240
#define S13_B1 20480
#define S13_B3 30720
#define SS13 40960
#define SMEM13 (3 * SS13)

__device__ __forceinline__ void load13(u32 sbase, int stage, int kt,
                                       const u16* Ah, const u16* Al,
                                       size_t wbase, int tid) {
    int k0 = kt * 32;
    u32 st = sbase + stage * SS13;
#pragma unroll
    for (int it = 0; it < 8; it++) {
        int c = tid + it * 256;
        int r = (c >> 2) & 127, ch = c & 3;
        u32 dst; const u16* src;
        if (c < 512)       { dst = st + S13_AH + r * RS + ch * 16; src = Ah + (size_t)r * DIM + k0 + ch * 8; }
        else if (c < 1024) { dst = st + S13_AL + r * RS + ch * 16; src = Al + (size_t)r * DIM + k0 + ch * 8; }
        else if (c < 1536) { dst = st + S13_B1 + r * RS + ch * 16; src = g_W1hi + (wbase + r) * DIM + k0 + ch * 8; }
        else               { dst = st + S13_B3 + r * RS + ch * 16; src = g_W3hi + (wbase + r) * DIM + k0 + ch * 8; }
        cpa16(dst, src);
    }
}

__global__ __launch_bounds__(256, 1)
void k_gemm13() {
    if ((int)blockIdx.x >= g_ntiles) return;
    extern __shared__ char smraw[];
    u32 sbase = smem_u32(smraw);
    int tid = threadIdx.x, wid = tid >> 5, lane = tid & 31;
    int warpM = wid >> 1, warpN = wid & 1;
    int e = g_tile_expert[blockIdx.x], row0 = g_tile_row0[blockIdx.x];
    int n0w = blockIdx.y * 128;

    const u16* Ah = g_Xhi + (size_t)row0 * DIM;
    const u16* Al = g_Xlo + (size_t)row0 * DIM;
    size_t wbase = (size_t)e * HID + n0w;

    u32 aoff = (u32)((lane & 15) * RS + (lane >> 4) * 16);
    u32 boff = (u32)((lane & 7) * RS + ((lane >> 3) & 1) * 16);
    u32 aW = (u32)(warpM * 32 * RS);
    u32 bW = (u32)(warpN * 64 * RS);

    float acc1[2][8][4], acc3[2][8][4];
#pragma unroll
    for (int mt = 0; mt < 2; mt++)
#pragma unroll
        for (int nt = 0; nt < 8; nt++)
#pragma unroll
            for (int j = 0; j < 4; j++) { acc1[mt][nt][j] = 0.f; acc3[mt][nt][j] = 0.f; }

    const int KT = DIM / 32;
    load13(sbase, 0, 0, Ah, Al, wbase, tid); cpa_commit();
    load13(sbase, 1, 1, Ah, Al, wbase, tid); cpa_commit();
    load13(sbase, 2, 2, Ah, Al, wbase, tid); cpa_commit();

    for (int kt = 0; kt < KT; kt++) {
        int stage = kt % 3;
        u32 st = sbase + stage * SS13;
        cpa_wait2();
        __syncthreads();
#pragma unroll
        for (int kh = 0; kh < 2; kh++) {
            u32 AH[2][4], AL[2][4];
#pragma unroll
            for (int mt = 0; mt < 2; mt++) {
                ldsm4(AH[mt], st + S13_AH + aW + mt * 16 * RS + kh * 32 + aoff);
                ldsm4(AL[mt], st + S13_AL + aW + mt * 16 * RS + kh * 32 + aoff);
            }
#pragma unroll
            for (int nt = 0; nt < 8; nt++) {
                u32 nb = bW + nt * 8 * RS + kh * 32 + boff;
                u32 b1h[2], b3h[2];
                ldsm2(b1h, st + S13_B1 + nb);
                ldsm2(b3h, st + S13_B3 + nb);
#pragma unroll
                for (int mt = 0; mt < 2; mt++) {
                    mma16816(acc1[mt][nt], AH[mt], b1h);
                    mma16816(acc1[mt][nt], AL[mt], b1h);
                    mma16816(acc3[mt][nt], AH[mt], b3h);
                    mma16816(acc3[mt][nt], AL[mt], b3h);
                }
            }
        }
        __syncthreads();
        if (kt + 3 < KT) load13(sbase, stage, kt + 3, Ah, Al, wbase, tid);
        cpa_commit();
    }

    int g4 = lane >> 2, t4 = lane & 3;
#pragma unroll
    for (int mt = 0; mt < 2; mt++) {
        int rA = row0 + warpM * 32 + mt * 16 + g4;
#pragma unroll
        for (int nt = 0; nt < 8; nt++) {
            int col = n0w + warpN * 64 + nt * 8 + t4 * 2;
            const float* d1 = acc1[mt][nt];
            const float* d3 = acc3[mt][nt];
#pragma unroll
            for (int half = 0; half < 2; half++) {
                int row = rA + half * 8;
                float r0 = fmaxf(d1[half * 2], 0.f), r1 = fmaxf(d1[half * 2 + 1], 0.f);
                float h0 = r0 * r0 * d3[half * 2];
                float h1 = r1 * r1 * d3[half * 2 + 1];
                u16 hh0 = f2h(h0), hh1 = f2h(h1);
                u16 ll0 = f2h(h0 - h2f(hh0)), ll1 = f2h(h1 - h2f(hh1));
                *(u32*)(g_Hhi + (size_t)row * HID + col) = pk(hh0, hh1);
                *(u32*)(g_Hlo + (size_t)row * HID + col) = pk(ll0, ll1);
            }
        }
    }
}

// ---------------- GEMM2: O = coef * (H W2^T) ----------------
// CTA 128 x 128, BK=32, 3-stage.
#define S2_AH 0
#define S2_AL 10240
#define S2_B  20480
#define SS2 30720
#define SMEM2 (3 * SS2)

__device__ __forceinline__ void load2(u32 sbase, int stage, int kt,
                                      const u16* Ah, const u16* Al,
                                      size_t wbase, int tid) {
    int k0 = kt * 32;
    u32 st = sbase + stage * SS2;
#pragma unroll
    for (int it = 0; it < 6; it++) {
        int c = tid + it * 256;
        int r = (c >> 2) & 127, ch = c & 3;
        u32 dst; const u16* src;
        if (c < 512)       { dst = st + S2_AH + r * RS + ch * 16; src = Ah + (size_t)r * HID + k0 + ch * 8; }
        else if (c < 1024) { dst = st + S2_AL + r * RS + ch * 16; src = Al + (size_t)r * HID + k0 + ch * 8; }
        else               { dst = st + S2_B + r * RS + ch * 16; src = g_W2hi + (wbase + r) * HID + k0 + ch * 8; }
        cpa16(dst, src);
    }
}

__global__ __launch_bounds__(256, 1)
void k_gemm2() {
    if ((int)blockIdx.x >= g_ntiles) return;
    extern __shared__ char smraw[];
    u32 sbase = smem_u32(smraw);
    int tid = threadIdx.x, wid = tid >> 5, lane = tid & 31;
    int warpM = wid >> 1, warpN = wid & 1;
    int e = g_tile_expert[blockIdx.x], row0 = g_tile_row0[blockIdx.x];
    int n0w = blockIdx.y * 128;

    const u16* Ah = g_Hhi + (size_t)row0 * HID;
    const u16* Al = g_Hlo + (size_t)row0 * HID;
    size_t wbase = (size_t)e * DIM + n0w;

    u32 aoff = (u32)((lane & 15) * RS + (lane >> 4) * 16);
    u32 boff = (u32)((lane & 7) * RS + ((lane >> 3) & 1) * 16);
    u32 aW = (u32)(warpM * 32 * RS);
    u32 bW = (u32)(warpN * 64 * RS);

    float acc[2][8][4];
#pragma unroll
    for (int mt = 0; mt < 2; mt++)
#pragma unroll
        for (int nt = 0; nt < 8; nt++)
#pragma unroll
            for (int j = 0; j < 4; j++) acc[mt][nt][j] = 0.f;

    const int KT = HID / 32;
    load2(sbase, 0, 0, Ah, Al, wbase, tid); cpa_commit();
    load2(sbase, 1, 1, Ah, Al, wbase, tid); cpa_commit();
    load2(sbase, 2, 2, Ah, Al, wbase, tid); cpa_commit();

    for (int kt = 0; kt < KT; kt++) {
        int stage = kt % 3;
        u32 st = sbase + stage * SS2;
        cpa_wait2();
        __syncthreads();
#pragma unroll
        for (int kh = 0; kh < 2; kh++) {
            u32 AH[2][4], AL[2][4];
#pragma unroll
            for (int mt = 0; mt < 2; mt++) {
                ldsm4(AH[mt], st + S2_AH + aW + mt * 16 * RS + kh * 32 + aoff);
                ldsm4(AL[mt], st + S2_AL + aW + mt * 16 * RS + kh * 32 + aoff);
            }
#pragma unroll
            for (int nt = 0; nt < 8; nt++) {
                u32 bh[2];
                ldsm2(bh, st + S2_B + bW + nt * 8 * RS + kh * 32 + boff);
#pragma unroll
                for (int mt = 0; mt < 2; mt++) {
                    mma16816(acc[mt][nt], AH[mt], bh);
                    mma16816(acc[mt][nt], AL[mt], bh);
                }
            }
        }
        __syncthreads();
        if (kt + 3 < KT) load2(sbase, stage, kt + 3, Ah, Al, wbase, tid);
        cpa_commit();
    }

    int g4 = lane >> 2, t4 = lane & 3;
#pragma unroll
    for (int mt = 0; mt < 2; mt++) {
        int rA = row0 + warpM * 32 + mt * 16 + g4;
        float c0 = g_row_coef[rA], c1 = g_row_coef[rA + 8];
#pragma unroll
        for (int nt = 0; nt < 8; nt++) {
            int col = n0w + warpN * 64 + nt * 8 + t4 * 2;
            const float* d = acc[mt][nt];
            *(float2*)(g_Orows + (size_t)rA * DIM + col) = make_float2(c0 * d[0], c0 * d[1]);
            *(float2*)(g_Orows + (size_t)(rA + 8) * DIM + col) = make_float2(c1 * d[2], c1 * d[3]);
        }
    }
}

__global__ void k_combine(float* __restrict__ out) {
    int t = blockIdx.x;
    int i = threadIdx.x * 4;
    int r0 = g_token_row[2 * t], r1 = g_token_row[2 * t + 1];
    float4 a = *(const float4*)(g_Orows + (size_t)r0 * DIM + i);
    float4 b = *(const float4*)(g_Orows + (size_t)r1 * DIM + i);
    *(float4*)(out + (size_t)t * DIM + i) =
        make_float4(a.x + b.x, a.y + b.y, a.z + b.z, a.w + b.w);
}

extern "C" void kernel_launch(void* const* d_in, const int* in_sizes, int n_in,
                              void* d_out, int out_size) {
    const float* x  = (const float*)d_in[0];
    const float* W1 = (const float*)d_in[1];
    const float* W2 = (const float*)d_in[2];
    const float* W3 = (const float*)d_in[3];
    const float* gw = (const float*)d_in[4];
    const float* gb = (const float*)d_in[5];
    float* out = (float*)d_out;

    cudaFuncSetAttribute(k_gemm13, cudaFuncAttributeMaxDynamicSharedMemorySize, SMEM13);
    cudaFuncSetAttribute(k_gemm2,  cudaFuncAttributeMaxDynamicSharedMemorySize, SMEM2);

    k_prep<<<49152, 256>>>(W1, W2, W3);
    k_gate<<<1024, 256>>>(x, gw, gb);
    k_offsets<<<1, 1>>>();
    k_assign<<<32, 256>>>();
    k_gather<<<MAXROWS, 256>>>(x);
    k_gemm13<<<dim3(MAXMT, HID / 128), 256, SMEM13>>>();
    k_gemm2<<<dim3(MAXMT, DIM / 128), 256, SMEM2>>>();
    k_combine<<<NTOK, 256>>>(out);
}

// round 6
// speedup vs baseline: 2.3791x; 1.3724x over previous
#include <cuda_runtime.h>
#include <cuda_fp16.h>
#include <cstdint>

typedef unsigned short u16;
typedef unsigned int   u32;
typedef unsigned long long u64;

#define NTOK 8192
#define DIM  1024
#define HID  2048
#define NE   8
#define MAXROWS 17408
#define MAXMT 136

__device__ int   g_counts[NE], g_fill[NE], g_seg[NE + 1], g_ntiles;
__device__ int   g_tile_expert[MAXMT], g_tile_row0[MAXMT];
__device__ int   g_row_token[MAXROWS];
__device__ float g_row_coef[MAXROWS];
__device__ int   g_token_row[NTOK * 2];
__device__ int   g_tok_e[NTOK * 2];
__device__ float g_tok_p[NTOK * 2];

__device__ __align__(16) u16 g_Xhi[(size_t)MAXROWS * DIM];
__device__ __align__(16) u16 g_Xlo[(size_t)MAXROWS * DIM];
__device__ __align__(16) u16 g_W1hi[(size_t)NE * HID * DIM];
__device__ __align__(16) u16 g_W3hi[(size_t)NE * HID * DIM];
__device__ __align__(16) u16 g_W2hi[(size_t)NE * DIM * HID];
__device__ __align__(16) u16 g_Hhi[(size_t)MAXROWS * HID];
__device__ __align__(16) float g_Orows[(size_t)MAXROWS * DIM];

__device__ __forceinline__ u16 f2h(float f) { return __half_as_ushort(__float2half_rn(f)); }
__device__ __forceinline__ float h2f(u16 u) { return __half2float(__ushort_as_half(u)); }
__device__ __forceinline__ u32 pk(u16 a, u16 b) { return (u32)a | ((u32)b << 16); }

__device__ __forceinline__ u32 smem_u32(const void* p) {
    u32 a;
    asm("{ .reg .u64 t; cvta.to.shared.u64 t, %1; cvt.u32.u64 %0, t; }" : "=r"(a) : "l"(p));
    return a;
}
__device__ __forceinline__ void cpa16(u32 dst, const void* src) {
    asm volatile("cp.async.cg.shared.global [%0], [%1], 16;" :: "r"(dst), "l"(src) : "memory");
}
__device__ __forceinline__ void cpa_commit() { asm volatile("cp.async.commit_group;" ::: "memory"); }
__device__ __forceinline__ void cpa_wait2() { asm volatile("cp.async.wait_group 2;" ::: "memory"); }

__device__ __forceinline__ void ldsm4(u32* r, u32 addr) {
    asm volatile("ldmatrix.sync.aligned.m8n8.x4.shared.b16 {%0,%1,%2,%3}, [%4];"
                 : "=r"(r[0]), "=r"(r[1]), "=r"(r[2]), "=r"(r[3]) : "r"(addr));
}
__device__ __forceinline__ void ldsm2(u32* r, u32 addr) {
    asm volatile("ldmatrix.sync.aligned.m8n8.x2.shared.b16 {%0,%1}, [%2];"
                 : "=r"(r[0]), "=r"(r[1]) : "r"(addr));
}
__device__ __forceinline__ void mma16816(float* c, const u32* a, const u32* b) {
    asm volatile(
        "mma.sync.aligned.m16n8k16.row.col.f32.f16.f16.f32 "
        "{%0,%1,%2,%3}, {%4,%5,%6,%7}, {%8,%9}, {%0,%1,%2,%3};"
        : "+f"(c[0]), "+f"(c[1]), "+f"(c[2]), "+f"(c[3])
        : "r"(a[0]), "r"(a[1]), "r"(a[2]), "r"(a[3]), "r"(b[0]), "r"(b[1]));
}

// ---------------- fused prep: init + weight fp16 conversion ----------------
__global__ void k_prep(const float* __restrict__ W1, const float* __restrict__ W2,
                       const float* __restrict__ W3) {
    int b = blockIdx.x;
    if (b < 68) {
        int i = b * 256 + threadIdx.x;
        if (i < MAXROWS) { g_row_token[i] = -1; g_row_coef[i] = 0.f; }
        if (i < NE) { g_counts[i] = 0; g_fill[i] = 0; }
    }
    int which = b >> 14;
    size_t i = ((size_t)(b & 16383) * 256 + threadIdx.x) * 4;
    const float* src = (which == 0) ? W1 : (which == 1) ? W3 : W2;
    u16* dst = (which == 0) ? g_W1hi : (which == 1) ? g_W3hi : g_W2hi;
    float4 v = *(const float4*)(src + i);
    *(uint2*)(dst + i) = make_uint2(pk(f2h(v.x), f2h(v.y)), pk(f2h(v.z), f2h(v.w)));
}

__global__ void k_gate(const float* __restrict__ x, const float* __restrict__ gw,
                       const float* __restrict__ gb) {
    int w = (blockIdx.x * blockDim.x + threadIdx.x) >> 5;
    int lane = threadIdx.x & 31;
    if (w >= NTOK) return;
    const float* xr = x + (size_t)w * DIM;
    float acc[NE];
#pragma unroll
    for (int e = 0; e < NE; e++) acc[e] = 0.f;
    for (int j = lane; j < DIM; j += 32) {
        float xv = xr[j];
#pragma unroll
        for (int e = 0; e < NE; e++) acc[e] = fmaf(xv, gw[e * DIM + j], acc[e]);
    }
#pragma unroll
    for (int e = 0; e < NE; e++)
#pragma unroll
        for (int o = 16; o; o >>= 1) acc[e] += __shfl_xor_sync(0xffffffffu, acc[e], o);
    if (lane == 0) {
#pragma unroll
        for (int e = 0; e < NE; e++) acc[e] += gb[e];
        int e0 = 0;
#pragma unroll
        for (int e = 1; e < NE; e++) if (acc[e] > acc[e0]) e0 = e;
        int e1 = (e0 == 0) ? 1 : 0;
#pragma unroll
        for (int e = 0; e < NE; e++) if (e != e0 && acc[e] > acc[e1]) e1 = e;
        float p0 = 1.f / (1.f + expf(acc[e1] - acc[e0]));
        g_tok_e[2 * w] = e0; g_tok_e[2 * w + 1] = e1;
        g_tok_p[2 * w] = p0; g_tok_p[2 * w + 1] = 1.f - p0;
        atomicAdd(&g_counts[e0], 1);
        atomicAdd(&g_counts[e1], 1);
    }
}

__global__ void k_offsets() {
    int off = 0, nt = 0;
    for (int e = 0; e < NE; e++) {
        g_seg[e] = off;
        int t = (g_counts[e] + 127) >> 7;
        for (int m = 0; m < t; m++) { g_tile_expert[nt] = e; g_tile_row0[nt] = off + (m << 7); nt++; }
        off += t << 7;
    }
    g_seg[NE] = off;
    g_ntiles = nt;
}

__global__ void k_assign() {
    int t = blockIdx.x * 256 + threadIdx.x;
    if (t >= NTOK) return;
#pragma unroll
    for (int k = 0; k < 2; k++) {
        int e = g_tok_e[2 * t + k];
        int row = g_seg[e] + atomicAdd(&g_fill[e], 1);
        g_row_token[row] = t;
        g_row_coef[row] = g_tok_p[2 * t + k];
        g_token_row[2 * t + k] = row;
    }
}

__global__ void k_gather(const float* __restrict__ x) {
    int row = blockIdx.x;
    int t = g_row_token[row];
    size_t off = (size_t)row * DIM + threadIdx.x * 4;
    float4 v = make_float4(0.f, 0.f, 0.f, 0.f);
    if (t >= 0) v = *(const float4*)(x + (size_t)t * DIM + threadIdx.x * 4);
    u16 h0 = f2h(v.x), h1 = f2h(v.y), h2 = f2h(v.z), h3 = f2h(v.w);
    u16 l0 = f2h(v.x - h2f(h0)), l1 = f2h(v.y - h2f(h1));
    u16 l2 = f2h(v.z - h2f(h2)), l3 = f2h(v.w - h2f(h3));
    *(uint2*)(g_Xhi + off) = make_uint2(pk(h0, h1), pk(h2, h3));
    *(uint2*)(g_Xlo + off) = make_uint2(pk(l0, l1), pk(l2, l3));
}

// ---------------- GEMM13: H = relu(X W1^T)^2 * (X W3^T) ----------------
// CTA 128(M) x 128(N), BK=32, 3-stage cp.async, rows padded to 80B.
// Warp tile 32(M) x 64(N); 8 warps = 4(M) x 2(N).
// acc1 = (Xh+Xl)·W1h (2 MMAs), acc3 = Xh·W3h (1 MMA).
#define RS 80
#define S13_AH 0
#define S13_AL 10240
#define S13_B1 20480
#define S13_B3 30720
#define SS13 40960
#define SMEM13 (3 * SS13)

__device__ __forceinline__ void load13(u32 sbase, int stage, int kt,
                                       const u16* Ah, const u16* Al,
                                       size_t wbase, int tid) {
    int k0 = kt * 32;
    u32 st = sbase + stage * SS13;
#pragma unroll
    for (int it = 0; it < 8; it++) {
        int c = tid + it * 256;
        int r = (c >> 2) & 127, ch = c & 3;
        u32 dst; const u16* src;
        if (c < 512)       { dst = st + S13_AH + r * RS + ch * 16; src = Ah + (size_t)r * DIM + k0 + ch * 8; }
        else if (c < 1024) { dst = st + S13_AL + r * RS + ch * 16; src = Al + (size_t)r * DIM + k0 + ch * 8; }
        else if (c < 1536) { dst = st + S13_B1 + r * RS + ch * 16; src = g_W1hi + (wbase + r) * DIM + k0 + ch * 8; }
        else               { dst = st + S13_B3 + r * RS + ch * 16; src = g_W3hi + (wbase + r) * DIM + k0 + ch * 8; }
        cpa16(dst, src);
    }
}

__global__ __launch_bounds__(256, 1)
void k_gemm13() {
    if ((int)blockIdx.x >= g_ntiles) return;
    extern __shared__ char smraw[];
    u32 sbase = smem_u32(smraw);
    int tid = threadIdx.x, wid = tid >> 5, lane = tid & 31;
    int warpM = wid >> 1, warpN = wid & 1;
    int e = g_tile_expert[blockIdx.x], row0 = g_tile_row0[blockIdx.x];
    int n0w = blockIdx.y * 128;

    const u16* Ah = g_Xhi + (size_t)row0 * DIM;
    const u16* Al = g_Xlo + (size_t)row0 * DIM;
    size_t wbase = (size_t)e * HID + n0w;

    u32 aoff = (u32)((lane & 15) * RS + (lane >> 4) * 16);
    u32 boff = (u32)((lane & 7) * RS + ((lane >> 3) & 1) * 16);
    u32 aW = (u32)(warpM * 32 * RS);
    u32 bW = (u32)(warpN * 64 * RS);

    float acc1[2][8][4], acc3[2][8][4];
#pragma unroll
    for (int mt = 0; mt < 2; mt++)
#pragma unroll
        for (int nt = 0; nt < 8; nt++)
#pragma unroll
            for (int j = 0; j < 4; j++) { acc1[mt][nt][j] = 0.f; acc3[mt][nt][j] = 0.f; }

    const int KT = DIM / 32;
    load13(sbase, 0, 0, Ah, Al, wbase, tid); cpa_commit();
    load13(sbase, 1, 1, Ah, Al, wbase, tid); cpa_commit();
    load13(sbase, 2, 2, Ah, Al, wbase, tid); cpa_commit();

    for (int kt = 0; kt < KT; kt++) {
        int stage = kt % 3;
        u32 st = sbase + stage * SS13;
        cpa_wait2();
        __syncthreads();
#pragma unroll
        for (int kh = 0; kh < 2; kh++) {
            u32 AH[2][4], AL[2][4];
#pragma unroll
            for (int mt = 0; mt < 2; mt++) {
                ldsm4(AH[mt], st + S13_AH + aW + mt * 16 * RS + kh * 32 + aoff);
                ldsm4(AL[mt], st + S13_AL + aW + mt * 16 * RS + kh * 32 + aoff);
            }
#pragma unroll
            for (int nt = 0; nt < 8; nt++) {
                u32 nb = bW + nt * 8 * RS + kh * 32 + boff;
                u32 b1h[2], b3h[2];
                ldsm2(b1h, st + S13_B1 + nb);
                ldsm2(b3h, st + S13_B3 + nb);
#pragma unroll
                for (int mt = 0; mt < 2; mt++) {
                    mma16816(acc1[mt][nt], AH[mt], b1h);
                    mma16816(acc1[mt][nt], AL[mt], b1h);
                    mma16816(acc3[mt][nt], AH[mt], b3h);
                }
            }
        }
        __syncthreads();
        if (kt + 3 < KT) load13(sbase, stage, kt + 3, Ah, Al, wbase, tid);
        cpa_commit();
    }

    int g4 = lane >> 2, t4 = lane & 3;
#pragma unroll
    for (int mt = 0; mt < 2; mt++) {
        int rA = row0 + warpM * 32 + mt * 16 + g4;
#pragma unroll
        for (int nt = 0; nt < 8; nt++) {
            int col = n0w + warpN * 64 + nt * 8 + t4 * 2;
            const float* d1 = acc1[mt][nt];
            const float* d3 = acc3[mt][nt];
#pragma unroll
            for (int half = 0; half < 2; half++) {
                int row = rA + half * 8;
                float r0 = fmaxf(d1[half * 2], 0.f), r1 = fmaxf(d1[half * 2 + 1], 0.f);
                float h0 = r0 * r0 * d3[half * 2];
                float h1 = r1 * r1 * d3[half * 2 + 1];
                *(u32*)(g_Hhi + (size_t)row * HID + col) = pk(f2h(h0), f2h(h1));
            }
        }
    }
}

// ---------------- GEMM2: O = coef * (H W2^T), single-term fp16 ----------------
// CTA 128 x 128, BK=32, 3-stage, 2 CTAs/SM.
#define S2_A 0
#define S2_B 10240
#define SS2 20480
#define SMEM2 (3 * SS2)

__device__ __forceinline__ void load2(u32 sbase, int stage, int kt,
                                      const u16* Ah, size_t wbase, int tid) {
    int k0 = kt * 32;
    u32 st = sbase + stage * SS2;
#pragma unroll
    for (int it = 0; it < 4; it++) {
        int c = tid + it * 256;
        int r = (c >> 2) & 127, ch = c & 3;
        u32 dst; const u16* src;
        if (c < 512) { dst = st + S2_A + r * RS + ch * 16; src = Ah + (size_t)r * HID + k0 + ch * 8; }
        else         { dst = st + S2_B + r * RS + ch * 16; src = g_W2hi + (wbase + r) * HID + k0 + ch * 8; }
        cpa16(dst, src);
    }
}

__global__ __launch_bounds__(256, 2)
void k_gemm2() {
    if ((int)blockIdx.x >= g_ntiles) return;
    extern __shared__ char smraw[];
    u32 sbase = smem_u32(smraw);
    int tid = threadIdx.x, wid = tid >> 5, lane = tid & 31;
    int warpM = wid >> 1, warpN = wid & 1;
    int e = g_tile_expert[blockIdx.x], row0 = g_tile_row0[blockIdx.x];
    int n0w = blockIdx.y * 128;

    const u16* Ah = g_Hhi + (size_t)row0 * HID;
    size_t wbase = (size_t)e * DIM + n0w;

    u32 aoff = (u32)((lane & 15) * RS + (lane >> 4) * 16);
    u32 boff = (u32)((lane & 7) * RS + ((lane >> 3) & 1) * 16);
    u32 aW = (u32)(warpM * 32 * RS);
    u32 bW = (u32)(warpN * 64 * RS);

    float acc[2][8][4];
#pragma unroll
    for (int mt = 0; mt < 2; mt++)
#pragma unroll
        for (int nt = 0; nt < 8; nt++)
#pragma unroll
            for (int j = 0; j < 4; j++) acc[mt][nt][j] = 0.f;

    const int KT = HID / 32;
    load2(sbase, 0, 0, Ah, wbase, tid); cpa_commit();
    load2(sbase, 1, 1, Ah, wbase, tid); cpa_commit();
    load2(sbase, 2, 2, Ah, wbase, tid); cpa_commit();

    for (int kt = 0; kt < KT; kt++) {
        int stage = kt % 3;
        u32 st = sbase + stage * SS2;
        cpa_wait2();
        __syncthreads();
#pragma unroll
        for (int kh = 0; kh < 2; kh++) {
            u32 AH[2][4];
#pragma unroll
            for (int mt = 0; mt < 2; mt++)
                ldsm4(AH[mt], st + S2_A + aW + mt * 16 * RS + kh * 32 + aoff);
#pragma unroll
            for (int nt = 0; nt < 8; nt++) {
                u32 bh[2];
                ldsm2(bh, st + S2_B + bW + nt * 8 * RS + kh * 32 + boff);
#pragma unroll
                for (int mt = 0; mt < 2; mt++)
                    mma16816(acc[mt][nt], AH[mt], bh);
            }
        }
        __syncthreads();
        if (kt + 3 < KT) load2(sbase, stage, kt + 3, Ah, wbase, tid);
        cpa_commit();
    }

    int g4 = lane >> 2, t4 = lane & 3;
#pragma unroll
    for (int mt = 0; mt < 2; mt++) {
        int rA = row0 + warpM * 32 + mt * 16 + g4;
        float c0 = g_row_coef[rA], c1 = g_row_coef[rA + 8];
#pragma unroll
        for (int nt = 0; nt < 8; nt++) {
            int col = n0w + warpN * 64 + nt * 8 + t4 * 2;
            const float* d = acc[mt][nt];
            *(float2*)(g_Orows + (size_t)rA * DIM + col) = make_float2(c0 * d[0], c0 * d[1]);
            *(float2*)(g_Orows + (size_t)(rA + 8) * DIM + col) = make_float2(c1 * d[2], c1 * d[3]);
        }
    }
}

__global__ void k_combine(float* __restrict__ out) {
    int t = blockIdx.x;
    int i = threadIdx.x * 4;
    int r0 = g_token_row[2 * t], r1 = g_token_row[2 * t + 1];
    float4 a = *(const float4*)(g_Orows + (size_t)r0 * DIM + i);
    float4 b = *(const float4*)(g_Orows + (size_t)r1 * DIM + i);
    *(float4*)(out + (size_t)t * DIM + i) =
        make_float4(a.x + b.x, a.y + b.y, a.z + b.z, a.w + b.w);
}

extern "C" void kernel_launch(void* const* d_in, const int* in_sizes, int n_in,
                              void* d_out, int out_size) {
    const float* x  = (const float*)d_in[0];
    const float* W1 = (const float*)d_in[1];
    const float* W2 = (const float*)d_in[2];
    const float* W3 = (const float*)d_in[3];
    const float* gw = (const float*)d_in[4];
    const float* gb = (const float*)d_in[5];
    float* out = (float*)d_out;

    cudaFuncSetAttribute(k_gemm13, cudaFuncAttributeMaxDynamicSharedMemorySize, SMEM13);
    cudaFuncSetAttribute(k_gemm2,  cudaFuncAttributeMaxDynamicSharedMemorySize, SMEM2);

    k_prep<<<49152, 256>>>(W1, W2, W3);
    k_gate<<<1024, 256>>>(x, gw, gb);
    k_offsets<<<1, 1>>>();
    k_assign<<<32, 256>>>();
    k_gather<<<MAXROWS, 256>>>(x);
    k_gemm13<<<dim3(MAXMT, HID / 128), 256, SMEM13>>>();
    k_gemm2<<<dim3(MAXMT, DIM / 128), 256, SMEM2>>>();
    k_combine<<<NTOK, 256>>>(out);
}

// round 7
// speedup vs baseline: 2.7467x; 1.1545x over previous
#include <cuda_runtime.h>
#include <cuda_fp16.h>
#include <cstdint>

typedef unsigned short u16;
typedef unsigned int   u32;
typedef unsigned long long u64;

#define NTOK 8192
#define DIM  1024
#define HID  2048
#define NE   8
#define MAXROWS 17408
#define MAXMT 136

__device__ int   g_counts[NE], g_fill[NE], g_seg[NE + 1], g_ntiles;
__device__ int   g_tile_expert[MAXMT], g_tile_row0[MAXMT];
__device__ int   g_row_token[MAXROWS];
__device__ float g_row_coef[MAXROWS];
__device__ int   g_token_row[NTOK * 2];
__device__ int   g_tok_e[NTOK * 2];
__device__ float g_tok_p[NTOK * 2];

__device__ __align__(16) u16 g_Xhi[(size_t)MAXROWS * DIM];
__device__ __align__(16) u16 g_W1hi[(size_t)NE * HID * DIM];
__device__ __align__(16) u16 g_W3hi[(size_t)NE * HID * DIM];
__device__ __align__(16) u16 g_W2hi[(size_t)NE * DIM * HID];
__device__ __align__(16) u16 g_Hhi[(size_t)MAXROWS * HID];
__device__ __align__(16) float g_Orows[(size_t)MAXROWS * DIM];

__device__ __forceinline__ u16 f2h(float f) { return __half_as_ushort(__float2half_rn(f)); }
__device__ __forceinline__ u32 pk(u16 a, u16 b) { return (u32)a | ((u32)b << 16); }

__device__ __forceinline__ u32 smem_u32(const void* p) {
    u32 a;
    asm("{ .reg .u64 t; cvta.to.shared.u64 t, %1; cvt.u32.u64 %0, t; }" : "=r"(a) : "l"(p));
    return a;
}
__device__ __forceinline__ void cpa16(u32 dst, const void* src) {
    asm volatile("cp.async.cg.shared.global [%0], [%1], 16;" :: "r"(dst), "l"(src) : "memory");
}
__device__ __forceinline__ void cpa_commit() { asm volatile("cp.async.commit_group;" ::: "memory"); }
__device__ __forceinline__ void cpa_wait2() { asm volatile("cp.async.wait_group 2;" ::: "memory"); }

__device__ __forceinline__ void ldsm4(u32* r, u32 addr) {
    asm volatile("ldmatrix.sync.aligned.m8n8.x4.shared.b16 {%0,%1,%2,%3}, [%4];"
                 : "=r"(r[0]), "=r"(r[1]), "=r"(r[2]), "=r"(r[3]) : "r"(addr));
}
__device__ __forceinline__ void ldsm2(u32* r, u32 addr) {
    asm volatile("ldmatrix.sync.aligned.m8n8.x2.shared.b16 {%0,%1}, [%2];"
                 : "=r"(r[0]), "=r"(r[1]) : "r"(addr));
}
__device__ __forceinline__ void mma16816(float* c, const u32* a, const u32* b) {
    asm volatile(
        "mma.sync.aligned.m16n8k16.row.col.f32.f16.f16.f32 "
        "{%0,%1,%2,%3}, {%4,%5,%6,%7}, {%8,%9}, {%0,%1,%2,%3};"
        : "+f"(c[0]), "+f"(c[1]), "+f"(c[2]), "+f"(c[3])
        : "r"(a[0]), "r"(a[1]), "r"(a[2]), "r"(a[3]), "r"(b[0]), "r"(b[1]));
}

// ---------------- fused prep: init + weight fp16 conversion ----------------
__global__ void k_prep(const float* __restrict__ W1, const float* __restrict__ W2,
                       const float* __restrict__ W3) {
    int b = blockIdx.x;
    if (b < 68) {
        int i = b * 256 + threadIdx.x;
        if (i < MAXROWS) { g_row_token[i] = -1; g_row_coef[i] = 0.f; }
        if (i < NE) { g_counts[i] = 0; g_fill[i] = 0; }
    }
    int which = b >> 14;
    size_t i = ((size_t)(b & 16383) * 256 + threadIdx.x) * 4;
    const float* src = (which == 0) ? W1 : (which == 1) ? W3 : W2;
    u16* dst = (which == 0) ? g_W1hi : (which == 1) ? g_W3hi : g_W2hi;
    float4 v = *(const float4*)(src + i);
    *(uint2*)(dst + i) = make_uint2(pk(f2h(v.x), f2h(v.y)), pk(f2h(v.z), f2h(v.w)));
}

__global__ void k_gate(const float* __restrict__ x, const float* __restrict__ gw,
                       const float* __restrict__ gb) {
    int w = (blockIdx.x * blockDim.x + threadIdx.x) >> 5;
    int lane = threadIdx.x & 31;
    if (w >= NTOK) return;
    const float* xr = x + (size_t)w * DIM;
    float acc[NE];
#pragma unroll
    for (int e = 0; e < NE; e++) acc[e] = 0.f;
    for (int j = lane; j < DIM; j += 32) {
        float xv = xr[j];
#pragma unroll
        for (int e = 0; e < NE; e++) acc[e] = fmaf(xv, gw[e * DIM + j], acc[e]);
    }
#pragma unroll
    for (int e = 0; e < NE; e++)
#pragma unroll
        for (int o = 16; o; o >>= 1) acc[e] += __shfl_xor_sync(0xffffffffu, acc[e], o);
    if (lane == 0) {
#pragma unroll
        for (int e = 0; e < NE; e++) acc[e] += gb[e];
        int e0 = 0;
#pragma unroll
        for (int e = 1; e < NE; e++) if (acc[e] > acc[e0]) e0 = e;
        int e1 = (e0 == 0) ? 1 : 0;
#pragma unroll
        for (int e = 0; e < NE; e++) if (e != e0 && acc[e] > acc[e1]) e1 = e;
        float p0 = 1.f / (1.f + expf(acc[e1] - acc[e0]));
        g_tok_e[2 * w] = e0; g_tok_e[2 * w + 1] = e1;
        g_tok_p[2 * w] = p0; g_tok_p[2 * w + 1] = 1.f - p0;
        atomicAdd(&g_counts[e0], 1);
        atomicAdd(&g_counts[e1], 1);
    }
}

__global__ void k_offsets() {
    int off = 0, nt = 0;
    for (int e = 0; e < NE; e++) {
        g_seg[e] = off;
        int t = (g_counts[e] + 127) >> 7;
        for (int m = 0; m < t; m++) { g_tile_expert[nt] = e; g_tile_row0[nt] = off + (m << 7); nt++; }
        off += t << 7;
    }
    g_seg[NE] = off;
    g_ntiles = nt;
}

__global__ void k_assign() {
    int t = blockIdx.x * 256 + threadIdx.x;
    if (t >= NTOK) return;
#pragma unroll
    for (int k = 0; k < 2; k++) {
        int e = g_tok_e[2 * t + k];
        int row = g_seg[e] + atomicAdd(&g_fill[e], 1);
        g_row_token[row] = t;
        g_row_coef[row] = g_tok_p[2 * t + k];
        g_token_row[2 * t + k] = row;
    }
}

__global__ void k_gather(const float* __restrict__ x) {
    int row = blockIdx.x;
    int t = g_row_token[row];
    size_t off = (size_t)row * DIM + threadIdx.x * 4;
    float4 v = make_float4(0.f, 0.f, 0.f, 0.f);
    if (t >= 0) v = *(const float4*)(x + (size_t)t * DIM + threadIdx.x * 4);
    *(uint2*)(g_Xhi + off) = make_uint2(pk(f2h(v.x), f2h(v.y)), pk(f2h(v.z), f2h(v.w)));
}

// ---------------- GEMM13: H = relu(X W1^T)^2 * (X W3^T) ----------------
// CTA 128(M) x 128(N), BK=32, 3-stage cp.async, rows padded to 80B.
// Warp tile 32(M) x 64(N); 8 warps = 4(M) x 2(N). 2 MMAs per subtile.
#define RS 80
#define S13_A  0
#define S13_B1 10240
#define S13_B3 20480
#define SS13 30720
#define SMEM13 (3 * SS13)

__device__ __forceinline__ void load13(u32 sbase, int stage, int kt,
                                       const u16* Ah, size_t wbase, int tid) {
    int k0 = kt * 32;
    u32 st = sbase + stage * SS13;
#pragma unroll
    for (int it = 0; it < 6; it++) {
        int c = tid + it * 256;
        int r = (c >> 2) & 127, ch = c & 3;
        u32 dst; const u16* src;
        if (c < 512)       { dst = st + S13_A + r * RS + ch * 16; src = Ah + (size_t)r * DIM + k0 + ch * 8; }
        else if (c < 1024) { dst = st + S13_B1 + r * RS + ch * 16; src = g_W1hi + (wbase + r) * DIM + k0 + ch * 8; }
        else               { dst = st + S13_B3 + r * RS + ch * 16; src = g_W3hi + (wbase + r) * DIM + k0 + ch * 8; }
        cpa16(dst, src);
    }
}

__global__ __launch_bounds__(256, 1)
void k_gemm13() {
    if ((int)blockIdx.x >= g_ntiles) return;
    extern __shared__ char smraw[];
    u32 sbase = smem_u32(smraw);
    int tid = threadIdx.x, wid = tid >> 5, lane = tid & 31;
    int warpM = wid >> 1, warpN = wid & 1;
    int e = g_tile_expert[blockIdx.x], row0 = g_tile_row0[blockIdx.x];
    int n0w = blockIdx.y * 128;

    const u16* Ah = g_Xhi + (size_t)row0 * DIM;
    size_t wbase = (size_t)e * HID + n0w;

    u32 aoff = (u32)((lane & 15) * RS + (lane >> 4) * 16);
    u32 boff = (u32)((lane & 7) * RS + ((lane >> 3) & 1) * 16);
    u32 aW = (u32)(warpM * 32 * RS);
    u32 bW = (u32)(warpN * 64 * RS);

    float acc1[2][8][4], acc3[2][8][4];
#pragma unroll
    for (int mt = 0; mt < 2; mt++)
#pragma unroll
        for (int nt = 0; nt < 8; nt++)
#pragma unroll
            for (int j = 0; j < 4; j++) { acc1[mt][nt][j] = 0.f; acc3[mt][nt][j] = 0.f; }

    const int KT = DIM / 32;
    load13(sbase, 0, 0, Ah, wbase, tid); cpa_commit();
    load13(sbase, 1, 1, Ah, wbase, tid); cpa_commit();
    load13(sbase, 2, 2, Ah, wbase, tid); cpa_commit();

    for (int kt = 0; kt < KT; kt++) {
        int stage = kt % 3;
        u32 st = sbase + stage * SS13;
        cpa_wait2();
        __syncthreads();
#pragma unroll
        for (int kh = 0; kh < 2; kh++) {
            u32 AH[2][4];
#pragma unroll
            for (int mt = 0; mt < 2; mt++)
                ldsm4(AH[mt], st + S13_A + aW + mt * 16 * RS + kh * 32 + aoff);
#pragma unroll
            for (int nt = 0; nt < 8; nt++) {
                u32 nb = bW + nt * 8 * RS + kh * 32 + boff;
                u32 b1h[2], b3h[2];
                ldsm2(b1h, st + S13_B1 + nb);
                ldsm2(b3h, st + S13_B3 + nb);
#pragma unroll
                for (int mt = 0; mt < 2; mt++) {
                    mma16816(acc1[mt][nt], AH[mt], b1h);
                    mma16816(acc3[mt][nt], AH[mt], b3h);
                }
            }
        }
        __syncthreads();
        if (kt + 3 < KT) load13(sbase, stage, kt + 3, Ah, wbase, tid);
        cpa_commit();
    }

    int g4 = lane >> 2, t4 = lane & 3;
#pragma unroll
    for (int mt = 0; mt < 2; mt++) {
        int rA = row0 + warpM * 32 + mt * 16 + g4;
#pragma unroll
        for (int nt = 0; nt < 8; nt++) {
            int col = n0w + warpN * 64 + nt * 8 + t4 * 2;
            const float* d1 = acc1[mt][nt];
            const float* d3 = acc3[mt][nt];
#pragma unroll
            for (int half = 0; half < 2; half++) {
                int row = rA + half * 8;
                float r0 = fmaxf(d1[half * 2], 0.f), r1 = fmaxf(d1[half * 2 + 1], 0.f);
                float h0 = r0 * r0 * d3[half * 2];
                float h1 = r1 * r1 * d3[half * 2 + 1];
                *(u32*)(g_Hhi + (size_t)row * HID + col) = pk(f2h(h0), f2h(h1));
            }
        }
    }
}

// ---------------- GEMM2: O = coef * (H W2^T), single-term fp16 ----------------
// CTA 128 x 128, BK=32, 3-stage, 2 CTAs/SM.
#define S2_A 0
#define S2_B 10240
#define SS2 20480
#define SMEM2 (3 * SS2)

__device__ __forceinline__ void load2(u32 sbase, int stage, int kt,
                                      const u16* Ah, size_t wbase, int tid) {
    int k0 = kt * 32;
    u32 st = sbase + stage * SS2;
#pragma unroll
    for (int it = 0; it < 4; it++) {
        int c = tid + it * 256;
        int r = (c >> 2) & 127, ch = c & 3;
        u32 dst; const u16* src;
        if (c < 512) { dst = st + S2_A + r * RS + ch * 16; src = Ah + (size_t)r * HID + k0 + ch * 8; }
        else         { dst = st + S2_B + r * RS + ch * 16; src = g_W2hi + (wbase + r) * HID + k0 + ch * 8; }
        cpa16(dst, src);
    }
}

__global__ __launch_bounds__(256, 2)
void k_gemm2() {
    if ((int)blockIdx.x >= g_ntiles) return;
    extern __shared__ char smraw[];
    u32 sbase = smem_u32(smraw);
    int tid = threadIdx.x, wid = tid >> 5, lane = tid & 31;
    int warpM = wid >> 1, warpN = wid & 1;
    int e = g_tile_expert[blockIdx.x], row0 = g_tile_row0[blockIdx.x];
    int n0w = blockIdx.y * 128;

    const u16* Ah = g_Hhi + (size_t)row0 * HID;
    size_t wbase = (size_t)e * DIM + n0w;

    u32 aoff = (u32)((lane & 15) * RS + (lane >> 4) * 16);
    u32 boff = (u32)((lane & 7) * RS + ((lane >> 3) & 1) * 16);
    u32 aW = (u32)(warpM * 32 * RS);
    u32 bW = (u32)(warpN * 64 * RS);

    float acc[2][8][4];
#pragma unroll
    for (int mt = 0; mt < 2; mt++)
#pragma unroll
        for (int nt = 0; nt < 8; nt++)
#pragma unroll
            for (int j = 0; j < 4; j++) acc[mt][nt][j] = 0.f;

    const int KT = HID / 32;
    load2(sbase, 0, 0, Ah, wbase, tid); cpa_commit();
    load2(sbase, 1, 1, Ah, wbase, tid); cpa_commit();
    load2(sbase, 2, 2, Ah, wbase, tid); cpa_commit();

    for (int kt = 0; kt < KT; kt++) {
        int stage = kt % 3;
        u32 st = sbase + stage * SS2;
        cpa_wait2();
        __syncthreads();
#pragma unroll
        for (int kh = 0; kh < 2; kh++) {
            u32 AH[2][4];
#pragma unroll
            for (int mt = 0; mt < 2; mt++)
                ldsm4(AH[mt], st + S2_A + aW + mt * 16 * RS + kh * 32 + aoff);
#pragma unroll
            for (int nt = 0; nt < 8; nt++) {
                u32 bh[2];
                ldsm2(bh, st + S2_B + bW + nt * 8 * RS + kh * 32 + boff);
#pragma unroll
                for (int mt = 0; mt < 2; mt++)
                    mma16816(acc[mt][nt], AH[mt], bh);
            }
        }
        __syncthreads();
        if (kt + 3 < KT) load2(sbase, stage, kt + 3, Ah, wbase, tid);
        cpa_commit();
    }

    int g4 = lane >> 2, t4 = lane & 3;
#pragma unroll
    for (int mt = 0; mt < 2; mt++) {
        int rA = row0 + warpM * 32 + mt * 16 + g4;
        float c0 = g_row_coef[rA], c1 = g_row_coef[rA + 8];
#pragma unroll
        for (int nt = 0; nt < 8; nt++) {
            int col = n0w + warpN * 64 + nt * 8 + t4 * 2;
            const float* d = acc[mt][nt];
            *(float2*)(g_Orows + (size_t)rA * DIM + col) = make_float2(c0 * d[0], c0 * d[1]);
            *(float2*)(g_Orows + (size_t)(rA + 8) * DIM + col) = make_float2(c1 * d[2], c1 * d[3]);
        }
    }
}

__global__ void k_combine(float* __restrict__ out) {
    int t = blockIdx.x;
    int i = threadIdx.x * 4;
    int r0 = g_token_row[2 * t], r1 = g_token_row[2 * t + 1];
    float4 a = *(const float4*)(g_Orows + (size_t)r0 * DIM + i);
    float4 b = *(const float4*)(g_Orows + (size_t)r1 * DIM + i);
    *(float4*)(out + (size_t)t * DIM + i) =
        make_float4(a.x + b.x, a.y + b.y, a.z + b.z, a.w + b.w);
}

extern "C" void kernel_launch(void* const* d_in, const int* in_sizes, int n_in,
                              void* d_out, int out_size) {
    const float* x  = (const float*)d_in[0];
    const float* W1 = (const float*)d_in[1];
    const float* W2 = (const float*)d_in[2];
    const float* W3 = (const float*)d_in[3];
    const float* gw = (const float*)d_in[4];
    const float* gb = (const float*)d_in[5];
    float* out = (float*)d_out;

    cudaFuncSetAttribute(k_gemm13, cudaFuncAttributeMaxDynamicSharedMemorySize, SMEM13);
    cudaFuncSetAttribute(k_gemm2,  cudaFuncAttributeMaxDynamicSharedMemorySize, SMEM2);

    k_prep<<<49152, 256>>>(W1, W2, W3);
    k_gate<<<1024, 256>>>(x, gw, gb);
    k_offsets<<<1, 1>>>();
    k_assign<<<32, 256>>>();
    k_gather<<<MAXROWS, 256>>>(x);
    k_gemm13<<<dim3(MAXMT, HID / 128), 256, SMEM13>>>();
    k_gemm2<<<dim3(MAXMT, DIM / 128), 256, SMEM2>>>();
    k_combine<<<NTOK, 256>>>(out);
}

// round 8
// speedup vs baseline: 2.7887x; 1.0153x over previous
#include <cuda_runtime.h>
#include <cuda_fp16.h>
#include <cstdint>

typedef unsigned short u16;
typedef unsigned int   u32;
typedef unsigned long long u64;

#define NTOK 8192
#define DIM  1024
#define HID  2048
#define NE   8
#define MAXROWS 17408
#define MAXMT 136

__device__ int   g_counts[NE], g_fill[NE], g_seg[NE + 1], g_ntiles;
__device__ int   g_tile_expert[MAXMT], g_tile_row0[MAXMT];
__device__ int   g_row_token[MAXROWS];
__device__ float g_row_coef[MAXROWS];
__device__ int   g_token_row[NTOK * 2];
__device__ int   g_tok_e[NTOK * 2];
__device__ float g_tok_p[NTOK * 2];

__device__ __align__(16) u16 g_Xhi[(size_t)MAXROWS * DIM];
__device__ __align__(16) u16 g_W1hi[(size_t)NE * HID * DIM];
__device__ __align__(16) u16 g_W3hi[(size_t)NE * HID * DIM];
__device__ __align__(16) u16 g_W2hi[(size_t)NE * DIM * HID];
__device__ __align__(16) u16 g_Hhi[(size_t)MAXROWS * HID];
__device__ __align__(16) float g_Orows[(size_t)MAXROWS * DIM];

__device__ __forceinline__ u16 f2h(float f) { return __half_as_ushort(__float2half_rn(f)); }
__device__ __forceinline__ u32 pk(u16 a, u16 b) { return (u32)a | ((u32)b << 16); }

__device__ __forceinline__ u32 smem_u32(const void* p) {
    u32 a;
    asm("{ .reg .u64 t; cvta.to.shared.u64 t, %1; cvt.u32.u64 %0, t; }" : "=r"(a) : "l"(p));
    return a;
}
__device__ __forceinline__ void cpa16(u32 dst, const void* src) {
    asm volatile("cp.async.cg.shared.global [%0], [%1], 16;" :: "r"(dst), "l"(src) : "memory");
}
__device__ __forceinline__ void cpa_commit() { asm volatile("cp.async.commit_group;" ::: "memory"); }
__device__ __forceinline__ void cpa_wait2() { asm volatile("cp.async.wait_group 2;" ::: "memory"); }

__device__ __forceinline__ void ldsm4(u32* r, u32 addr) {
    asm volatile("ldmatrix.sync.aligned.m8n8.x4.shared.b16 {%0,%1,%2,%3}, [%4];"
                 : "=r"(r[0]), "=r"(r[1]), "=r"(r[2]), "=r"(r[3]) : "r"(addr));
}
__device__ __forceinline__ void ldsm2(u32* r, u32 addr) {
    asm volatile("ldmatrix.sync.aligned.m8n8.x2.shared.b16 {%0,%1}, [%2];"
                 : "=r"(r[0]), "=r"(r[1]) : "r"(addr));
}
__device__ __forceinline__ void mma16816(float* c, const u32* a, const u32* b) {
    asm volatile(
        "mma.sync.aligned.m16n8k16.row.col.f32.f16.f16.f32 "
        "{%0,%1,%2,%3}, {%4,%5,%6,%7}, {%8,%9}, {%0,%1,%2,%3};"
        : "+f"(c[0]), "+f"(c[1]), "+f"(c[2]), "+f"(c[3])
        : "r"(a[0]), "r"(a[1]), "r"(a[2]), "r"(a[3]), "r"(b[0]), "r"(b[1]));
}

// ---------------- fused prep: init + weight fp16 conversion ----------------
__global__ void k_prep(const float* __restrict__ W1, const float* __restrict__ W2,
                       const float* __restrict__ W3) {
    int b = blockIdx.x;
    if (b < 68) {
        int i = b * 256 + threadIdx.x;
        if (i < MAXROWS) { g_row_token[i] = -1; g_row_coef[i] = 0.f; }
        if (i < NE) { g_counts[i] = 0; g_fill[i] = 0; }
    }
    int which = b >> 14;
    size_t i = ((size_t)(b & 16383) * 256 + threadIdx.x) * 4;
    const float* src = (which == 0) ? W1 : (which == 1) ? W3 : W2;
    u16* dst = (which == 0) ? g_W1hi : (which == 1) ? g_W3hi : g_W2hi;
    float4 v = *(const float4*)(src + i);
    *(uint2*)(dst + i) = make_uint2(pk(f2h(v.x), f2h(v.y)), pk(f2h(v.z), f2h(v.w)));
}

__global__ void k_gate(const float* __restrict__ x, const float* __restrict__ gw,
                       const float* __restrict__ gb) {
    int w = (blockIdx.x * blockDim.x + threadIdx.x) >> 5;
    int lane = threadIdx.x & 31;
    if (w >= NTOK) return;
    const float* xr = x + (size_t)w * DIM;
    float acc[NE];
#pragma unroll
    for (int e = 0; e < NE; e++) acc[e] = 0.f;
    for (int j = lane; j < DIM; j += 32) {
        float xv = xr[j];
#pragma unroll
        for (int e = 0; e < NE; e++) acc[e] = fmaf(xv, gw[e * DIM + j], acc[e]);
    }
#pragma unroll
    for (int e = 0; e < NE; e++)
#pragma unroll
        for (int o = 16; o; o >>= 1) acc[e] += __shfl_xor_sync(0xffffffffu, acc[e], o);
    if (lane == 0) {
#pragma unroll
        for (int e = 0; e < NE; e++) acc[e] += gb[e];
        int e0 = 0;
#pragma unroll
        for (int e = 1; e < NE; e++) if (acc[e] > acc[e0]) e0 = e;
        int e1 = (e0 == 0) ? 1 : 0;
#pragma unroll
        for (int e = 0; e < NE; e++) if (e != e0 && acc[e] > acc[e1]) e1 = e;
        float p0 = 1.f / (1.f + expf(acc[e1] - acc[e0]));
        g_tok_e[2 * w] = e0; g_tok_e[2 * w + 1] = e1;
        g_tok_p[2 * w] = p0; g_tok_p[2 * w + 1] = 1.f - p0;
        atomicAdd(&g_counts[e0], 1);
        atomicAdd(&g_counts[e1], 1);
    }
}

__global__ void k_offsets() {
    int off = 0, nt = 0;
    for (int e = 0; e < NE; e++) {
        g_seg[e] = off;
        int t = (g_counts[e] + 127) >> 7;
        for (int m = 0; m < t; m++) { g_tile_expert[nt] = e; g_tile_row0[nt] = off + (m << 7); nt++; }
        off += t << 7;
    }
    g_seg[NE] = off;
    g_ntiles = nt;
}

__global__ void k_assign() {
    int t = blockIdx.x * 256 + threadIdx.x;
    if (t >= NTOK) return;
#pragma unroll
    for (int k = 0; k < 2; k++) {
        int e = g_tok_e[2 * t + k];
        int row = g_seg[e] + atomicAdd(&g_fill[e], 1);
        g_row_token[row] = t;
        g_row_coef[row] = g_tok_p[2 * t + k];
        g_token_row[2 * t + k] = row;
    }
}

__global__ void k_gather(const float* __restrict__ x) {
    int row = blockIdx.x;
    int t = g_row_token[row];
    size_t off = (size_t)row * DIM + threadIdx.x * 4;
    float4 v = make_float4(0.f, 0.f, 0.f, 0.f);
    if (t >= 0) v = *(const float4*)(x + (size_t)t * DIM + threadIdx.x * 4);
    *(uint2*)(g_Xhi + off) = make_uint2(pk(f2h(v.x), f2h(v.y)), pk(f2h(v.z), f2h(v.w)));
}

// ---------------- GEMM13: H = relu(X W1^T)^2 * (X W3^T) ----------------
// CTA 128(M) x 128(N), BK=32, 4-stage cp.async, single barrier per K-tile.
// Warp tile 32(M) x 64(N); 8 warps = 4(M) x 2(N). 2 MMAs per subtile.
#define RS 80
#define S13_A  0
#define S13_B1 10240
#define S13_B3 20480
#define SS13 30720
#define SMEM13 (4 * SS13)

__device__ __forceinline__ void load13(u32 sbase, int stage, int kt,
                                       const u16* Ah, size_t wbase, int tid) {
    int k0 = kt * 32;
    u32 st = sbase + stage * SS13;
#pragma unroll
    for (int it = 0; it < 6; it++) {
        int c = tid + it * 256;
        int r = (c >> 2) & 127, ch = c & 3;
        u32 dst; const u16* src;
        if (c < 512)       { dst = st + S13_A + r * RS + ch * 16; src = Ah + (size_t)r * DIM + k0 + ch * 8; }
        else if (c < 1024) { dst = st + S13_B1 + r * RS + ch * 16; src = g_W1hi + (wbase + r) * DIM + k0 + ch * 8; }
        else               { dst = st + S13_B3 + r * RS + ch * 16; src = g_W3hi + (wbase + r) * DIM + k0 + ch * 8; }
        cpa16(dst, src);
    }
}

__global__ __launch_bounds__(256, 1)
void k_gemm13() {
    if ((int)blockIdx.x >= g_ntiles) return;
    extern __shared__ char smraw[];
    u32 sbase = smem_u32(smraw);
    int tid = threadIdx.x, wid = tid >> 5, lane = tid & 31;
    int warpM = wid >> 1, warpN = wid & 1;
    int e = g_tile_expert[blockIdx.x], row0 = g_tile_row0[blockIdx.x];
    int n0w = blockIdx.y * 128;

    const u16* Ah = g_Xhi + (size_t)row0 * DIM;
    size_t wbase = (size_t)e * HID + n0w;

    u32 aoff = (u32)((lane & 15) * RS + (lane >> 4) * 16);
    u32 boff = (u32)((lane & 7) * RS + ((lane >> 3) & 1) * 16);
    u32 aW = (u32)(warpM * 32 * RS);
    u32 bW = (u32)(warpN * 64 * RS);

    float acc1[2][8][4], acc3[2][8][4];
#pragma unroll
    for (int mt = 0; mt < 2; mt++)
#pragma unroll
        for (int nt = 0; nt < 8; nt++)
#pragma unroll
            for (int j = 0; j < 4; j++) { acc1[mt][nt][j] = 0.f; acc3[mt][nt][j] = 0.f; }

    const int KT = DIM / 32;
    load13(sbase, 0, 0, Ah, wbase, tid); cpa_commit();
    load13(sbase, 1, 1, Ah, wbase, tid); cpa_commit();
    load13(sbase, 2, 2, Ah, wbase, tid); cpa_commit();

    for (int kt = 0; kt < KT; kt++) {
        cpa_wait2();
        __syncthreads();
        if (kt + 3 < KT) load13(sbase, (kt + 3) & 3, kt + 3, Ah, wbase, tid);
        cpa_commit();
        u32 st = sbase + (kt & 3) * SS13;
#pragma unroll
        for (int kh = 0; kh < 2; kh++) {
            u32 AH[2][4];
#pragma unroll
            for (int mt = 0; mt < 2; mt++)
                ldsm4(AH[mt], st + S13_A + aW + mt * 16 * RS + kh * 32 + aoff);
#pragma unroll
            for (int nt = 0; nt < 8; nt++) {
                u32 nb = bW + nt * 8 * RS + kh * 32 + boff;
                u32 b1h[2], b3h[2];
                ldsm2(b1h, st + S13_B1 + nb);
                ldsm2(b3h, st + S13_B3 + nb);
#pragma unroll
                for (int mt = 0; mt < 2; mt++) {
                    mma16816(acc1[mt][nt], AH[mt], b1h);
                    mma16816(acc3[mt][nt], AH[mt], b3h);
                }
            }
        }
    }

    int g4 = lane >> 2, t4 = lane & 3;
#pragma unroll
    for (int mt = 0; mt < 2; mt++) {
        int rA = row0 + warpM * 32 + mt * 16 + g4;
#pragma unroll
        for (int nt = 0; nt < 8; nt++) {
            int col = n0w + warpN * 64 + nt * 8 + t4 * 2;
            const float* d1 = acc1[mt][nt];
            const float* d3 = acc3[mt][nt];
#pragma unroll
            for (int half = 0; half < 2; half++) {
                int row = rA + half * 8;
                float r0 = fmaxf(d1[half * 2], 0.f), r1 = fmaxf(d1[half * 2 + 1], 0.f);
                float h0 = r0 * r0 * d3[half * 2];
                float h1 = r1 * r1 * d3[half * 2 + 1];
                *(u32*)(g_Hhi + (size_t)row * HID + col) = pk(f2h(h0), f2h(h1));
            }
        }
    }
}

// ---------------- GEMM2: O = coef * (H W2^T), single-term fp16 ----------------
// CTA 128 x 128, BK=32, 4-stage, single barrier, 2 CTAs/SM.
#define S2_A 0
#define S2_B 10240
#define SS2 20480
#define SMEM2 (4 * SS2)

__device__ __forceinline__ void load2(u32 sbase, int stage, int kt,
                                      const u16* Ah, size_t wbase, int tid) {
    int k0 = kt * 32;
    u32 st = sbase + stage * SS2;
#pragma unroll
    for (int it = 0; it < 4; it++) {
        int c = tid + it * 256;
        int r = (c >> 2) & 127, ch = c & 3;
        u32 dst; const u16* src;
        if (c < 512) { dst = st + S2_A + r * RS + ch * 16; src = Ah + (size_t)r * HID + k0 + ch * 8; }
        else         { dst = st + S2_B + r * RS + ch * 16; src = g_W2hi + (wbase + r) * HID + k0 + ch * 8; }
        cpa16(dst, src);
    }
}

__global__ __launch_bounds__(256, 2)
void k_gemm2() {
    if ((int)blockIdx.x >= g_ntiles) return;
    extern __shared__ char smraw[];
    u32 sbase = smem_u32(smraw);
    int tid = threadIdx.x, wid = tid >> 5, lane = tid & 31;
    int warpM = wid >> 1, warpN = wid & 1;
    int e = g_tile_expert[blockIdx.x], row0 = g_tile_row0[blockIdx.x];
    int n0w = blockIdx.y * 128;

    const u16* Ah = g_Hhi + (size_t)row0 * HID;
    size_t wbase = (size_t)e * DIM + n0w;

    u32 aoff = (u32)((lane & 15) * RS + (lane >> 4) * 16);
    u32 boff = (u32)((lane & 7) * RS + ((lane >> 3) & 1) * 16);
    u32 aW = (u32)(warpM * 32 * RS);
    u32 bW = (u32)(warpN * 64 * RS);

    float acc[2][8][4];
#pragma unroll
    for (int mt = 0; mt < 2; mt++)
#pragma unroll
        for (int nt = 0; nt < 8; nt++)
#pragma unroll
            for (int j = 0; j < 4; j++) acc[mt][nt][j] = 0.f;

    const int KT = HID / 32;
    load2(sbase, 0, 0, Ah, wbase, tid); cpa_commit();
    load2(sbase, 1, 1, Ah, wbase, tid); cpa_commit();
    load2(sbase, 2, 2, Ah, wbase, tid); cpa_commit();

    for (int kt = 0; kt < KT; kt++) {
        cpa_wait2();
        __syncthreads();
        if (kt + 3 < KT) load2(sbase, (kt + 3) & 3, kt + 3, Ah, wbase, tid);
        cpa_commit();
        u32 st = sbase + (kt & 3) * SS2;
#pragma unroll
        for (int kh = 0; kh < 2; kh++) {
            u32 AH[2][4];
#pragma unroll
            for (int mt = 0; mt < 2; mt++)
                ldsm4(AH[mt], st + S2_A + aW + mt * 16 * RS + kh * 32 + aoff);
#pragma unroll
            for (int nt = 0; nt < 8; nt++) {
                u32 bh[2];
                ldsm2(bh, st + S2_B + bW + nt * 8 * RS + kh * 32 + boff);
#pragma unroll
                for (int mt = 0; mt < 2; mt++)
                    mma16816(acc[mt][nt], AH[mt], bh);
            }
        }
    }

    int g4 = lane >> 2, t4 = lane & 3;
#pragma unroll
    for (int mt = 0; mt < 2; mt++) {
        int rA = row0 + warpM * 32 + mt * 16 + g4;
        float c0 = g_row_coef[rA], c1 = g_row_coef[rA + 8];
#pragma unroll
        for (int nt = 0; nt < 8; nt++) {
            int col = n0w + warpN * 64 + nt * 8 + t4 * 2;
            const float* d = acc[mt][nt];
            *(float2*)(g_Orows + (size_t)rA * DIM + col) = make_float2(c0 * d[0], c0 * d[1]);
            *(float2*)(g_Orows + (size_t)(rA + 8) * DIM + col) = make_float2(c1 * d[2], c1 * d[3]);
        }
    }
}

__global__ void k_combine(float* __restrict__ out) {
    int t = blockIdx.x;
    int i = threadIdx.x * 4;
    int r0 = g_token_row[2 * t], r1 = g_token_row[2 * t + 1];
    float4 a = *(const float4*)(g_Orows + (size_t)r0 * DIM + i);
    float4 b = *(const float4*)(g_Orows + (size_t)r1 * DIM + i);
    *(float4*)(out + (size_t)t * DIM + i) =
        make_float4(a.x + b.x, a.y + b.y, a.z + b.z, a.w + b.w);
}

extern "C" void kernel_launch(void* const* d_in, const int* in_sizes, int n_in,
                              void* d_out, int out_size) {
    const float* x  = (const float*)d_in[0];
    const float* W1 = (const float*)d_in[1];
    const float* W2 = (const float*)d_in[2];
    const float* W3 = (const float*)d_in[3];
    const float* gw = (const float*)d_in[4];
    const float* gb = (const float*)d_in[5];
    float* out = (float*)d_out;

    cudaFuncSetAttribute(k_gemm13, cudaFuncAttributeMaxDynamicSharedMemorySize, SMEM13);
    cudaFuncSetAttribute(k_gemm2,  cudaFuncAttributeMaxDynamicSharedMemorySize, SMEM2);

    k_prep<<<49152, 256>>>(W1, W2, W3);
    k_gate<<<1024, 256>>>(x, gw, gb);
    k_offsets<<<1, 1>>>();
    k_assign<<<32, 256>>>();
    k_gather<<<MAXROWS, 256>>>(x);
    k_gemm13<<<dim3(MAXMT, HID / 128), 256, SMEM13>>>();
    k_gemm2<<<dim3(MAXMT, DIM / 128), 256, SMEM2>>>();
    k_combine<<<NTOK, 256>>>(out);
}

// round 9
// speedup vs baseline: 2.9622x; 1.0622x over previous
#include <cuda_runtime.h>
#include <cuda_fp16.h>
#include <cstdint>

typedef unsigned short u16;
typedef unsigned int   u32;
typedef unsigned long long u64;

#define NTOK 8192
#define DIM  1024
#define HID  2048
#define NE   8
#define MAXROWS 17408
#define MAXMT 136

__device__ int   g_counts[NE], g_fill[NE], g_seg[NE + 1], g_ntiles;
__device__ int   g_tile_expert[MAXMT], g_tile_row0[MAXMT];
__device__ int   g_row_token[MAXROWS];
__device__ float g_row_coef[MAXROWS];
__device__ int   g_token_row[NTOK * 2];
__device__ int   g_tok_e[NTOK * 2];
__device__ float g_tok_p[NTOK * 2];

__device__ __align__(16) u16 g_Xhi[(size_t)MAXROWS * DIM];
__device__ __align__(16) u16 g_W1hi[(size_t)NE * HID * DIM];
__device__ __align__(16) u16 g_W3hi[(size_t)NE * HID * DIM];
__device__ __align__(16) u16 g_W2hi[(size_t)NE * DIM * HID];
__device__ __align__(16) u16 g_Hhi[(size_t)MAXROWS * HID];
__device__ __align__(16) float g_Orows[(size_t)MAXROWS * DIM];

__device__ __forceinline__ u16 f2h(float f) { return __half_as_ushort(__float2half_rn(f)); }
__device__ __forceinline__ u32 pk(u16 a, u16 b) { return (u32)a | ((u32)b << 16); }

__device__ __forceinline__ u32 smem_u32(const void* p) {
    u32 a;
    asm("{ .reg .u64 t; cvta.to.shared.u64 t, %1; cvt.u32.u64 %0, t; }" : "=r"(a) : "l"(p));
    return a;
}
__device__ __forceinline__ void cpa16(u32 dst, const void* src) {
    asm volatile("cp.async.cg.shared.global [%0], [%1], 16;" :: "r"(dst), "l"(src) : "memory");
}
__device__ __forceinline__ void cpa_commit() { asm volatile("cp.async.commit_group;" ::: "memory"); }
__device__ __forceinline__ void cpa_wait2() { asm volatile("cp.async.wait_group 2;" ::: "memory"); }

__device__ __forceinline__ void ldsm4(u32* r, u32 addr) {
    asm volatile("ldmatrix.sync.aligned.m8n8.x4.shared.b16 {%0,%1,%2,%3}, [%4];"
                 : "=r"(r[0]), "=r"(r[1]), "=r"(r[2]), "=r"(r[3]) : "r"(addr));
}
__device__ __forceinline__ void ldsm2(u32* r, u32 addr) {
    asm volatile("ldmatrix.sync.aligned.m8n8.x2.shared.b16 {%0,%1}, [%2];"
                 : "=r"(r[0]), "=r"(r[1]) : "r"(addr));
}
__device__ __forceinline__ void mma16816(float* c, const u32* a, const u32* b) {
    asm volatile(
        "mma.sync.aligned.m16n8k16.row.col.f32.f16.f16.f32 "
        "{%0,%1,%2,%3}, {%4,%5,%6,%7}, {%8,%9}, {%0,%1,%2,%3};"
        : "+f"(c[0]), "+f"(c[1]), "+f"(c[2]), "+f"(c[3])
        : "r"(a[0]), "r"(a[1]), "r"(a[2]), "r"(a[3]), "r"(b[0]), "r"(b[1]));
}

// ---------------- fused prep: init + weight fp16 conversion ----------------
__global__ void k_prep(const float* __restrict__ W1, const float* __restrict__ W2,
                       const float* __restrict__ W3) {
    int b = blockIdx.x;
    if (b < 68) {
        int i = b * 256 + threadIdx.x;
        if (i < MAXROWS) { g_row_token[i] = -1; g_row_coef[i] = 0.f; }
        if (i < NE) { g_counts[i] = 0; g_fill[i] = 0; }
    }
    int which = b >> 14;
    size_t i = ((size_t)(b & 16383) * 256 + threadIdx.x) * 4;
    const float* src = (which == 0) ? W1 : (which == 1) ? W3 : W2;
    u16* dst = (which == 0) ? g_W1hi : (which == 1) ? g_W3hi : g_W2hi;
    float4 v = *(const float4*)(src + i);
    *(uint2*)(dst + i) = make_uint2(pk(f2h(v.x), f2h(v.y)), pk(f2h(v.z), f2h(v.w)));
}

__global__ void k_gate(const float* __restrict__ x, const float* __restrict__ gw,
                       const float* __restrict__ gb) {
    int w = (blockIdx.x * blockDim.x + threadIdx.x) >> 5;
    int lane = threadIdx.x & 31;
    if (w >= NTOK) return;
    const float* xr = x + (size_t)w * DIM;
    float acc[NE];
#pragma unroll
    for (int e = 0; e < NE; e++) acc[e] = 0.f;
    for (int j = lane; j < DIM; j += 32) {
        float xv = xr[j];
#pragma unroll
        for (int e = 0; e < NE; e++) acc[e] = fmaf(xv, gw[e * DIM + j], acc[e]);
    }
#pragma unroll
    for (int e = 0; e < NE; e++)
#pragma unroll
        for (int o = 16; o; o >>= 1) acc[e] += __shfl_xor_sync(0xffffffffu, acc[e], o);
    if (lane == 0) {
#pragma unroll
        for (int e = 0; e < NE; e++) acc[e] += gb[e];
        int e0 = 0;
#pragma unroll
        for (int e = 1; e < NE; e++) if (acc[e] > acc[e0]) e0 = e;
        int e1 = (e0 == 0) ? 1 : 0;
#pragma unroll
        for (int e = 0; e < NE; e++) if (e != e0 && acc[e] > acc[e1]) e1 = e;
        float p0 = 1.f / (1.f + expf(acc[e1] - acc[e0]));
        g_tok_e[2 * w] = e0; g_tok_e[2 * w + 1] = e1;
        g_tok_p[2 * w] = p0; g_tok_p[2 * w + 1] = 1.f - p0;
        atomicAdd(&g_counts[e0], 1);
        atomicAdd(&g_counts[e1], 1);
    }
}

__global__ void k_offsets() {
    int off = 0, nt = 0;
    for (int e = 0; e < NE; e++) {
        g_seg[e] = off;
        int t = (g_counts[e] + 127) >> 7;
        for (int m = 0; m < t; m++) { g_tile_expert[nt] = e; g_tile_row0[nt] = off + (m << 7); nt++; }
        off += t << 7;
    }
    g_seg[NE] = off;
    g_ntiles = nt;
}

__global__ void k_assign() {
    int t = blockIdx.x * 256 + threadIdx.x;
    if (t >= NTOK) return;
#pragma unroll
    for (int k = 0; k < 2; k++) {
        int e = g_tok_e[2 * t + k];
        int row = g_seg[e] + atomicAdd(&g_fill[e], 1);
        g_row_token[row] = t;
        g_row_coef[row] = g_tok_p[2 * t + k];
        g_token_row[2 * t + k] = row;
    }
}

__global__ void k_gather(const float* __restrict__ x) {
    int row = blockIdx.x;
    int t = g_row_token[row];
    size_t off = (size_t)row * DIM + threadIdx.x * 4;
    float4 v = make_float4(0.f, 0.f, 0.f, 0.f);
    if (t >= 0) v = *(const float4*)(x + (size_t)t * DIM + threadIdx.x * 4);
    *(uint2*)(g_Xhi + off) = make_uint2(pk(f2h(v.x), f2h(v.y)), pk(f2h(v.z), f2h(v.w)));
}

// ---------------- GEMM13: H = relu(X W1^T)^2 * (X W3^T) ----------------
// CTA 128(M) x 128(N), 512 threads (16 warps = 4 warps/SMSP), warp tile 32x32.
// BK=32, 4-stage cp.async, single barrier per K-tile.
#define RS 80
#define S13_A  0
#define S13_B1 10240
#define S13_B3 20480
#define SS13 30720
#define SMEM13 (4 * SS13)

__device__ __forceinline__ void load13(u32 sbase, int stage, int kt,
                                       const u16* Ah, size_t wbase, int tid) {
    int k0 = kt * 32;
    u32 st = sbase + stage * SS13;
#pragma unroll
    for (int it = 0; it < 3; it++) {
        int c = tid + it * 512;
        int r = (c >> 2) & 127, ch = c & 3;
        u32 dst; const u16* src;
        if (c < 512)       { dst = st + S13_A + r * RS + ch * 16; src = Ah + (size_t)r * DIM + k0 + ch * 8; }
        else if (c < 1024) { dst = st + S13_B1 + r * RS + ch * 16; src = g_W1hi + (wbase + r) * DIM + k0 + ch * 8; }
        else               { dst = st + S13_B3 + r * RS + ch * 16; src = g_W3hi + (wbase + r) * DIM + k0 + ch * 8; }
        cpa16(dst, src);
    }
}

__global__ __launch_bounds__(512, 1)
void k_gemm13() {
    if ((int)blockIdx.x >= g_ntiles) return;
    extern __shared__ char smraw[];
    u32 sbase = smem_u32(smraw);
    int tid = threadIdx.x, wid = tid >> 5, lane = tid & 31;
    int warpM = wid >> 2, warpN = wid & 3;
    int e = g_tile_expert[blockIdx.x], row0 = g_tile_row0[blockIdx.x];
    int n0w = blockIdx.y * 128;

    const u16* Ah = g_Xhi + (size_t)row0 * DIM;
    size_t wbase = (size_t)e * HID + n0w;

    u32 aoff = (u32)((lane & 15) * RS + (lane >> 4) * 16);
    u32 boff = (u32)((lane & 7) * RS + ((lane >> 3) & 1) * 16);
    u32 aW = (u32)(warpM * 32 * RS);
    u32 bW = (u32)(warpN * 32 * RS);

    float acc1[2][4][4], acc3[2][4][4];
#pragma unroll
    for (int mt = 0; mt < 2; mt++)
#pragma unroll
        for (int nt = 0; nt < 4; nt++)
#pragma unroll
            for (int j = 0; j < 4; j++) { acc1[mt][nt][j] = 0.f; acc3[mt][nt][j] = 0.f; }

    const int KT = DIM / 32;
    load13(sbase, 0, 0, Ah, wbase, tid); cpa_commit();
    load13(sbase, 1, 1, Ah, wbase, tid); cpa_commit();
    load13(sbase, 2, 2, Ah, wbase, tid); cpa_commit();

    for (int kt = 0; kt < KT; kt++) {
        cpa_wait2();
        __syncthreads();
        if (kt + 3 < KT) load13(sbase, (kt + 3) & 3, kt + 3, Ah, wbase, tid);
        cpa_commit();
        u32 st = sbase + (kt & 3) * SS13;
#pragma unroll
        for (int kh = 0; kh < 2; kh++) {
            u32 AH[2][4];
#pragma unroll
            for (int mt = 0; mt < 2; mt++)
                ldsm4(AH[mt], st + S13_A + aW + mt * 16 * RS + kh * 32 + aoff);
#pragma unroll
            for (int nt = 0; nt < 4; nt++) {
                u32 nb = bW + nt * 8 * RS + kh * 32 + boff;
                u32 b1h[2], b3h[2];
                ldsm2(b1h, st + S13_B1 + nb);
                ldsm2(b3h, st + S13_B3 + nb);
#pragma unroll
                for (int mt = 0; mt < 2; mt++) {
                    mma16816(acc1[mt][nt], AH[mt], b1h);
                    mma16816(acc3[mt][nt], AH[mt], b3h);
                }
            }
        }
    }

    int g4 = lane >> 2, t4 = lane & 3;
#pragma unroll
    for (int mt = 0; mt < 2; mt++) {
        int rA = row0 + warpM * 32 + mt * 16 + g4;
#pragma unroll
        for (int nt = 0; nt < 4; nt++) {
            int col = n0w + warpN * 32 + nt * 8 + t4 * 2;
            const float* d1 = acc1[mt][nt];
            const float* d3 = acc3[mt][nt];
#pragma unroll
            for (int half = 0; half < 2; half++) {
                int row = rA + half * 8;
                float r0 = fmaxf(d1[half * 2], 0.f), r1 = fmaxf(d1[half * 2 + 1], 0.f);
                float h0 = r0 * r0 * d3[half * 2];
                float h1 = r1 * r1 * d3[half * 2 + 1];
                *(u32*)(g_Hhi + (size_t)row * HID + col) = pk(f2h(h0), f2h(h1));
            }
        }
    }
}

// ---------------- GEMM2: O = coef * (H W2^T), single-term fp16 ----------------
// CTA 128 x 128, 512 threads (16 warps), warp tile 32x32, BK=32, 4-stage.
#define S2_A 0
#define S2_B 10240
#define SS2 20480
#define SMEM2 (4 * SS2)

__device__ __forceinline__ void load2(u32 sbase, int stage, int kt,
                                      const u16* Ah, size_t wbase, int tid) {
    int k0 = kt * 32;
    u32 st = sbase + stage * SS2;
#pragma unroll
    for (int it = 0; it < 2; it++) {
        int c = tid + it * 512;
        int r = (c >> 2) & 127, ch = c & 3;
        u32 dst; const u16* src;
        if (c < 512) { dst = st + S2_A + r * RS + ch * 16; src = Ah + (size_t)r * HID + k0 + ch * 8; }
        else         { dst = st + S2_B + r * RS + ch * 16; src = g_W2hi + (wbase + r) * HID + k0 + ch * 8; }
        cpa16(dst, src);
    }
}

__global__ __launch_bounds__(512, 1)
void k_gemm2() {
    if ((int)blockIdx.x >= g_ntiles) return;
    extern __shared__ char smraw[];
    u32 sbase = smem_u32(smraw);
    int tid = threadIdx.x, wid = tid >> 5, lane = tid & 31;
    int warpM = wid >> 2, warpN = wid & 3;
    int e = g_tile_expert[blockIdx.x], row0 = g_tile_row0[blockIdx.x];
    int n0w = blockIdx.y * 128;

    const u16* Ah = g_Hhi + (size_t)row0 * HID;
    size_t wbase = (size_t)e * DIM + n0w;

    u32 aoff = (u32)((lane & 15) * RS + (lane >> 4) * 16);
    u32 boff = (u32)((lane & 7) * RS + ((lane >> 3) & 1) * 16);
    u32 aW = (u32)(warpM * 32 * RS);
    u32 bW = (u32)(warpN * 32 * RS);

    float acc[2][4][4];
#pragma unroll
    for (int mt = 0; mt < 2; mt++)
#pragma unroll
        for (int nt = 0; nt < 4; nt++)
#pragma unroll
            for (int j = 0; j < 4; j++) acc[mt][nt][j] = 0.f;

    const int KT = HID / 32;
    load2(sbase, 0, 0, Ah, wbase, tid); cpa_commit();
    load2(sbase, 1, 1, Ah, wbase, tid); cpa_commit();
    load2(sbase, 2, 2, Ah, wbase, tid); cpa_commit();

    for (int kt = 0; kt < KT; kt++) {
        cpa_wait2();
        __syncthreads();
        if (kt + 3 < KT) load2(sbase, (kt + 3) & 3, kt + 3, Ah, wbase, tid);
        cpa_commit();
        u32 st = sbase + (kt & 3) * SS2;
#pragma unroll
        for (int kh = 0; kh < 2; kh++) {
            u32 AH[2][4];
#pragma unroll
            for (int mt = 0; mt < 2; mt++)
                ldsm4(AH[mt], st + S2_A + aW + mt * 16 * RS + kh * 32 + aoff);
#pragma unroll
            for (int nt = 0; nt < 4; nt++) {
                u32 bh[2];
                ldsm2(bh, st + S2_B + bW + nt * 8 * RS + kh * 32 + boff);
#pragma unroll
                for (int mt = 0; mt < 2; mt++)
                    mma16816(acc[mt][nt], AH[mt], bh);
            }
        }
    }

    int g4 = lane >> 2, t4 = lane & 3;
#pragma unroll
    for (int mt = 0; mt < 2; mt++) {
        int rA = row0 + warpM * 32 + mt * 16 + g4;
        float c0 = g_row_coef[rA], c1 = g_row_coef[rA + 8];
#pragma unroll
        for (int nt = 0; nt < 4; nt++) {
            int col = n0w + warpN * 32 + nt * 8 + t4 * 2;
            const float* d = acc[mt][nt];
            *(float2*)(g_Orows + (size_t)rA * DIM + col) = make_float2(c0 * d[0], c0 * d[1]);
            *(float2*)(g_Orows + (size_t)(rA + 8) * DIM + col) = make_float2(c1 * d[2], c1 * d[3]);
        }
    }
}

__global__ void k_combine(float* __restrict__ out) {
    int t = blockIdx.x;
    int i = threadIdx.x * 4;
    int r0 = g_token_row[2 * t], r1 = g_token_row[2 * t + 1];
    float4 a = *(const float4*)(g_Orows + (size_t)r0 * DIM + i);
    float4 b = *(const float4*)(g_Orows + (size_t)r1 * DIM + i);
    *(float4*)(out + (size_t)t * DIM + i) =
        make_float4(a.x + b.x, a.y + b.y, a.z + b.z, a.w + b.w);
}

extern "C" void kernel_launch(void* const* d_in, const int* in_sizes, int n_in,
                              void* d_out, int out_size) {
    const float* x  = (const float*)d_in[0];
    const float* W1 = (const float*)d_in[1];
    const float* W2 = (const float*)d_in[2];
    const float* W3 = (const float*)d_in[3];
    const float* gw = (const float*)d_in[4];
    const float* gb = (const float*)d_in[5];
    float* out = (float*)d_out;

    cudaFuncSetAttribute(k_gemm13, cudaFuncAttributeMaxDynamicSharedMemorySize, SMEM13);
    cudaFuncSetAttribute(k_gemm2,  cudaFuncAttributeMaxDynamicSharedMemorySize, SMEM2);

    k_prep<<<49152, 256>>>(W1, W2, W3);
    k_gate<<<1024, 256>>>(x, gw, gb);
    k_offsets<<<1, 1>>>();
    k_assign<<<32, 256>>>();
    k_gather<<<MAXROWS, 256>>>(x);
    k_gemm13<<<dim3(MAXMT, HID / 128), 512, SMEM13>>>();
    k_gemm2<<<dim3(MAXMT, DIM / 128), 512, SMEM2>>>();
    k_combine<<<NTOK, 256>>>(out);
}